// round 5
// baseline (speedup 1.0000x reference)
#include <cuda_runtime.h>
#include <cuda_bf16.h>
#include <stdint.h>
#include <math.h>

#define T_ 64
#define B_ 32
#define V_ 32000
#define H_ 1024
#define K0_ 2560
#define K1_ 2048

// ---------------- device scratch (no allocations allowed) ----------------
__device__ float dW0[4096 * K0_];                 // [W_ih0 | W_hh0]
__device__ float dW1[4096 * K1_];                 // [W_ih1 | W_hh1]
__device__ float dWkT[H_ * H_];                   // Wk transposed
__device__ float dB0[4096], dB1[4096];
__device__ __nv_bfloat16 dWp[(size_t)V_ * H_];
__device__ float dX0[B_ * K0_];                   // [emb | feed | h0_prev]
__device__ float dX1[B_ * K1_];                   // [h0_new | h1_prev]
__device__ float dXc[B_ * K1_];                   // [htop | summary]
__device__ float dG0[2 * 4096 * B_];              // split-K partials, j-major
__device__ float dG1[2 * 4096 * B_];
__device__ float dQ[H_ * B_];
__device__ float dGc[2 * H_ * B_];
__device__ float dC0[H_ * B_], dC1[H_ * B_];      // cell states, [h][b]
__device__ float dHB[(size_t)T_ * B_ * H_];       // hbuf [t][b][h]
__device__ float dDist[T_ * T_ * B_];             // [t][s][b]
__device__ __nv_bfloat16 dA[(size_t)T_ * B_ * H_];// comb bf16, row = t*32+b
__device__ float dMx[T_ * B_], dIs[T_ * B_], dCw[T_ * B_];
__device__ float dLog[(size_t)T_ * B_ * V_];

__device__ __forceinline__ float sigf(float x) { return 1.0f / (1.0f + expf(-x)); }

__device__ __forceinline__ void mma8(float c[4], unsigned a0, unsigned a1,
                                     unsigned a2, unsigned a3, unsigned b0, unsigned b1) {
    asm volatile("mma.sync.aligned.m16n8k8.row.col.f32.tf32.tf32.f32 "
                 "{%0,%1,%2,%3},{%4,%5,%6,%7},{%8,%9},{%0,%1,%2,%3};"
                 : "+f"(c[0]), "+f"(c[1]), "+f"(c[2]), "+f"(c[3])
                 : "r"(a0), "r"(a1), "r"(a2), "r"(a3), "r"(b0), "r"(b1));
}
__device__ __forceinline__ void mma16(float c[4], unsigned a0, unsigned a1,
                                      unsigned a2, unsigned a3, unsigned b0, unsigned b1) {
    asm volatile("mma.sync.aligned.m16n8k16.row.col.f32.bf16.bf16.f32 "
                 "{%0,%1,%2,%3},{%4,%5,%6,%7},{%8,%9},{%0,%1,%2,%3};"
                 : "+f"(c[0]), "+f"(c[1]), "+f"(c[2]), "+f"(c[3])
                 : "r"(a0), "r"(a1), "r"(a2), "r"(a3), "r"(b0), "r"(b1));
}

// ---------------- prep ----------------
__global__ void pk_w0(const float* __restrict__ Wih, const float* __restrict__ Whh) {
    for (size_t i = (size_t)blockIdx.x * blockDim.x + threadIdx.x; i < (size_t)4096 * K0_;
         i += (size_t)gridDim.x * blockDim.x) {
        size_t j = i / K0_, k = i % K0_;
        dW0[i] = (k < 1536) ? Wih[j * 1536 + k] : Whh[j * 1024 + (k - 1536)];
    }
}
__global__ void pk_w1(const float* __restrict__ Wih, const float* __restrict__ Whh) {
    for (size_t i = (size_t)blockIdx.x * blockDim.x + threadIdx.x; i < (size_t)4096 * K1_;
         i += (size_t)gridDim.x * blockDim.x) {
        size_t j = i / K1_, k = i % K1_;
        dW1[i] = (k < 1024) ? Wih[j * 1024 + k] : Whh[j * 1024 + (k - 1024)];
    }
}
__global__ void pk_wp(const float* __restrict__ Wp) {
    for (size_t i = (size_t)blockIdx.x * blockDim.x + threadIdx.x; i < (size_t)V_ * H_;
         i += (size_t)gridDim.x * blockDim.x)
        dWp[i] = __float2bfloat16(Wp[i]);
}
__global__ void pk_misc(const float* __restrict__ Wk, const float* __restrict__ bih0,
                        const float* __restrict__ bhh0, const float* __restrict__ bih1,
                        const float* __restrict__ bhh1, const float* __restrict__ h0,
                        const float* __restrict__ c0, const float* __restrict__ Eb,
                        const int* __restrict__ tok) {
    for (size_t i = (size_t)blockIdx.x * blockDim.x + threadIdx.x; i < (size_t)H_ * H_;
         i += (size_t)gridDim.x * blockDim.x) {
        // Wk transpose: dWkT[j][k] = Wk[k][j]
        { size_t j = i / H_, k = i % H_; dWkT[i] = Wk[k * H_ + j]; }
        if (i < 4096) { dB0[i] = bih0[i] + bhh0[i]; dB1[i] = bih1[i] + bhh1[i]; }
        if (i < (size_t)B_ * H_) {       // states
            int b = (int)(i / H_), h = (int)(i % H_);
            dC0[h * 32 + b] = c0[(size_t)b * H_ + h];
            dC1[h * 32 + b] = c0[(size_t)B_ * H_ + (size_t)b * H_ + h];
            dX1[b * K1_ + 1024 + h] = h0[(size_t)B_ * H_ + (size_t)b * H_ + h];
            dX0[b * K0_ + 1536 + h] = h0[(size_t)b * H_ + h];
            dX0[b * K0_ + 512 + h] = 0.0f;   // feed = 0
        }
        if (i < (size_t)B_ * 512) {      // emb for t=0
            int b = (int)(i / 512), e = (int)(i % 512);
            dX0[b * K0_ + e] = Eb[(size_t)tok[b] * 512 + e];
        }
    }
}

// ---------------- per-step tf32 GEMM: Out[j][b] = sum_k W[j][k]*X[b][k] ----------------
// grid.x = J/64, grid.y = ksplit; partial s written at Out + y*J*32
__global__ void gemm_step(const float* __restrict__ W, const float* __restrict__ X,
                          float* __restrict__ Out, int K) {
    int Kh = K / gridDim.y;
    int k0 = blockIdx.y * Kh;
    int j0 = blockIdx.x * 64;
    int w = threadIdx.x >> 5, lane = threadIdx.x & 31;
    int g = lane >> 2, tg = lane & 3;
    int mo = (w & 3) * 16, no = (w >> 2) * 16;
    float c[2][4] = {};
    const float* Wr = W + (size_t)(j0 + mo) * K + k0;
    const float* Xr = X + (size_t)no * K + k0;
#pragma unroll 4
    for (int kc = 0; kc < Kh; kc += 8) {
        unsigned a0 = __float_as_uint(Wr[(size_t)g * K + kc + tg]);
        unsigned a1 = __float_as_uint(Wr[(size_t)(g + 8) * K + kc + tg]);
        unsigned a2 = __float_as_uint(Wr[(size_t)g * K + kc + tg + 4]);
        unsigned a3 = __float_as_uint(Wr[(size_t)(g + 8) * K + kc + tg + 4]);
        unsigned b0 = __float_as_uint(Xr[(size_t)g * K + kc + tg]);
        unsigned b1 = __float_as_uint(Xr[(size_t)g * K + kc + tg + 4]);
        unsigned b2 = __float_as_uint(Xr[(size_t)(g + 8) * K + kc + tg]);
        unsigned b3 = __float_as_uint(Xr[(size_t)(g + 8) * K + kc + tg + 4]);
        mma8(c[0], a0, a1, a2, a3, b0, b1);
        mma8(c[1], a0, a1, a2, a3, b2, b3);
    }
    int J = gridDim.x * 64;
    float* O = Out + (size_t)blockIdx.y * J * 32;
#pragma unroll
    for (int nt = 0; nt < 2; nt++) {
        int n = no + nt * 8 + tg * 2;
        O[(size_t)(j0 + mo + g) * 32 + n] = c[nt][0];
        O[(size_t)(j0 + mo + g) * 32 + n + 1] = c[nt][1];
        O[(size_t)(j0 + mo + g + 8) * 32 + n] = c[nt][2];
        O[(size_t)(j0 + mo + g + 8) * 32 + n + 1] = c[nt][3];
    }
}

// ---------------- LSTM pointwise ----------------
__global__ void pw0(void) {
    int i = blockIdx.x * blockDim.x + threadIdx.x;   // 32768
    int b = i & 31, h = i >> 5;
    const int S = 4096 * 32;
    float gi = dG0[h * 32 + b] + dG0[S + h * 32 + b] + dB0[h];
    float gf = dG0[(1024 + h) * 32 + b] + dG0[S + (1024 + h) * 32 + b] + dB0[1024 + h];
    float gg = dG0[(2048 + h) * 32 + b] + dG0[S + (2048 + h) * 32 + b] + dB0[2048 + h];
    float go = dG0[(3072 + h) * 32 + b] + dG0[S + (3072 + h) * 32 + b] + dB0[3072 + h];
    float cn = sigf(gf) * dC0[i] + sigf(gi) * tanhf(gg);
    float hn = sigf(go) * tanhf(cn);
    dC0[i] = cn;
    dX1[b * K1_ + h] = hn;            // layer1 input (this step)
    dX0[b * K0_ + 1536 + h] = hn;     // layer0 h input (next step)
}
__global__ void pw1(int t) {
    int i = blockIdx.x * blockDim.x + threadIdx.x;
    int b = i & 31, h = i >> 5;
    const int S = 4096 * 32;
    float gi = dG1[h * 32 + b] + dG1[S + h * 32 + b] + dB1[h];
    float gf = dG1[(1024 + h) * 32 + b] + dG1[S + (1024 + h) * 32 + b] + dB1[1024 + h];
    float gg = dG1[(2048 + h) * 32 + b] + dG1[S + (2048 + h) * 32 + b] + dB1[2048 + h];
    float go = dG1[(3072 + h) * 32 + b] + dG1[S + (3072 + h) * 32 + b] + dB1[3072 + h];
    float cn = sigf(gf) * dC1[i] + sigf(gi) * tanhf(gg);
    float hn = sigf(go) * tanhf(cn);
    dC1[i] = cn;
    dX1[b * K1_ + 1024 + h] = hn;                      // h1_prev (next step)
    dHB[((size_t)t * 32 + b) * H_ + h] = hn;           // hbuf[t]
}

// ---------------- attention (block per batch element) ----------------
__global__ void attn(int t, const int* __restrict__ tok, const float* __restrict__ bk) {
    int b = blockIdx.x, tid = threadIdx.x;
    __shared__ float qv[H_];
    __shared__ float sc[T_];
    __shared__ float red[256];
    const float* ht = dHB + ((size_t)t * 32 + b) * H_;
    for (int h = tid; h < H_; h += 256) qv[h] = dQ[h * 32 + b];
    float s = 0.f;
    for (int h = tid; h < H_; h += 256) s += bk[h] * ht[h];
    red[tid] = s; __syncthreads();
    for (int st = 128; st; st >>= 1) { if (tid < st) red[tid] += red[tid + st]; __syncthreads(); }
    float bkh = red[0];
    __syncthreads();
    int w = tid >> 5, lane = tid & 31;
    for (int si = w; si <= t; si += 8) {
        const float* hr = dHB + ((size_t)si * 32 + b) * H_;
        float acc = 0.f;
        for (int h = lane; h < H_; h += 32) acc += hr[h] * qv[h];
#pragma unroll
        for (int o = 16; o; o >>= 1) acc += __shfl_xor_sync(0xffffffffu, acc, o);
        if (!lane) {
            float v = acc + bkh;
            if (tok[si * 32 + b] == 0) v += -99999.0f;
            sc[si] = v;
        }
    }
    __syncthreads();
    if (tid == 0) {
        float m = -1e30f;
        for (int s2 = 0; s2 <= t; s2++) m = fmaxf(m, sc[s2]);
        float sum = 0.f;
        for (int s2 = 0; s2 <= t; s2++) { float e = expf(sc[s2] - m); sc[s2] = e; sum += e; }
        float inv = 1.0f / sum;
        for (int s2 = 0; s2 <= t; s2++) sc[s2] *= inv;
    }
    __syncthreads();
    for (int s2 = tid; s2 < T_; s2 += 256)
        dDist[(t * T_ + s2) * 32 + b] = (s2 <= t) ? sc[s2] : 0.0f;
    for (int h = tid; h < H_; h += 256) {
        float acc = 0.f;
        for (int s2 = 0; s2 <= t; s2++) acc += sc[s2] * dHB[((size_t)s2 * 32 + b) * H_ + h];
        dXc[b * K1_ + 1024 + h] = acc;
        dXc[b * K1_ + h] = ht[h];
    }
}

// ---------------- comb store: feed + bf16 A matrix + next-step emb ----------------
__global__ void store_comb(int t, const float* __restrict__ bc,
                           const float* __restrict__ Eb, const int* __restrict__ tok) {
    int i = blockIdx.x * blockDim.x + threadIdx.x;   // 32768
    int b = i & 31, j = i >> 5;
    float v = dGc[j * 32 + b] + dGc[32768 + j * 32 + b] + bc[j];
    dX0[b * K0_ + 512 + j] = v;
    dA[((size_t)t * 32 + b) * H_ + j] = __float2bfloat16(v);
    if (t + 1 < T_ && j < 512)
        dX0[b * K0_ + j] = Eb[(size_t)tok[(t + 1) * 32 + b] * 512 + j];
}

// ---------------- final logits GEMM (bf16 tensor cores) ----------------
__global__ void gemm_logits(const float* __restrict__ bp) {
    int v0 = blockIdx.x * 64, r0 = blockIdx.y * 64;
    __shared__ __nv_bfloat16 As[64][16];
    __shared__ __nv_bfloat16 Bs[64][16];
    int tid = threadIdx.x, w = tid >> 5, lane = tid & 31;
    int g = lane >> 2, tg = lane & 3;
    int mo = (w & 3) * 16, no = (w >> 2) * 32;
    int lrow = tid >> 2, lcol = (tid & 3) * 4;
    float c[4][4] = {};
    for (int k0 = 0; k0 < H_; k0 += 16) {
        *(uint2*)&As[lrow][lcol] = *(const uint2*)&dA[((size_t)r0 + lrow) * H_ + k0 + lcol];
        *(uint2*)&Bs[lrow][lcol] = *(const uint2*)&dWp[((size_t)v0 + lrow) * H_ + k0 + lcol];
        __syncthreads();
        unsigned a0 = *(unsigned*)&As[mo + g][tg * 2];
        unsigned a1 = *(unsigned*)&As[mo + g + 8][tg * 2];
        unsigned a2 = *(unsigned*)&As[mo + g][tg * 2 + 8];
        unsigned a3 = *(unsigned*)&As[mo + g + 8][tg * 2 + 8];
#pragma unroll
        for (int nt = 0; nt < 4; nt++) {
            unsigned b0 = *(unsigned*)&Bs[no + nt * 8 + g][tg * 2];
            unsigned b1 = *(unsigned*)&Bs[no + nt * 8 + g][tg * 2 + 8];
            mma16(c[nt], a0, a1, a2, a3, b0, b1);
        }
        __syncthreads();
    }
#pragma unroll
    for (int nt = 0; nt < 4; nt++) {
        int v = v0 + no + nt * 8 + tg * 2;
        size_t o = (size_t)(r0 + mo + g) * V_ + v;
        dLog[o] = c[nt][0] + bp[v];
        dLog[o + 1] = c[nt][1] + bp[v + 1];
        size_t o2 = o + (size_t)8 * V_;
        dLog[o2] = c[nt][2] + bp[v];
        dLog[o2 + 1] = c[nt][3] + bp[v + 1];
    }
}

// ---------------- softmax + mixture log output ----------------
__global__ void softmax_out(float* __restrict__ out) {
    int r = blockIdx.x, tid = threadIdx.x;
    const float* L = dLog + (size_t)r * V_;
    __shared__ float red[256];
    float m = -1e30f;
    for (int v = tid; v < V_; v += 256) m = fmaxf(m, L[v]);
    red[tid] = m; __syncthreads();
    for (int st = 128; st; st >>= 1) { if (tid < st) red[tid] = fmaxf(red[tid], red[tid + st]); __syncthreads(); }
    m = red[0]; __syncthreads();
    float s = 0.f;
    for (int v = tid; v < V_; v += 256) s += __expf(L[v] - m);
    red[tid] = s; __syncthreads();
    for (int st = 128; st; st >>= 1) { if (tid < st) red[tid] += red[tid + st]; __syncthreads(); }
    s = red[0];
    float inv = 1.0f / s;
    float cw = __expf(L[3] - m) * inv;        // COPY_ID = 3
    if (tid == 0) { dMx[r] = m; dIs[r] = inv; dCw[r] = cw; }
    float ce = cw * 1e-7f, oc = 1.0f - cw;
    float* O = out + (size_t)r * V_;
    for (int v = tid; v < V_; v += 256)
        O[v] = __logf(ce + oc * __expf(L[v] - m) * inv);
}

// copy-distribution fixup: overwrite the <=64 token columns per row
__global__ void fixup(float* __restrict__ out, const int* __restrict__ tok) {
    int r = blockIdx.x;                 // r = t*32+b
    int t = r >> 5, b = r & 31;
    int s = threadIdx.x;                // 64 threads
    __shared__ int tk[T_];
    __shared__ float dd[T_];
    tk[s] = tok[s * 32 + b];
    dd[s] = dDist[(t * T_ + s) * 32 + b];
    __syncthreads();
    int mytok = tk[s];
    float tot = 0.f;
    for (int s2 = 0; s2 < T_; s2++) if (tk[s2] == mytok) tot += dd[s2];
    float m = dMx[r], inv = dIs[r], cw = dCw[r];
    float p = __expf(dLog[(size_t)r * V_ + mytok] - m) * inv;
    out[(size_t)r * V_ + mytok] = __logf(cw * (1e-7f + tot) + (1.0f - cw) * p);
}

// ---------------- host ----------------
extern "C" void kernel_launch(void* const* d_in, const int* in_sizes, int n_in,
                              void* d_out, int out_size) {
    const int* tok = (const int*)d_in[0];
    const float* h0 = (const float*)d_in[1];
    const float* c0 = (const float*)d_in[2];
    const float* Eb = (const float*)d_in[3];
    const float* Wih0 = (const float*)d_in[4];
    const float* Whh0 = (const float*)d_in[5];
    const float* bih0 = (const float*)d_in[6];
    const float* bhh0 = (const float*)d_in[7];
    const float* Wih1 = (const float*)d_in[8];
    const float* Whh1 = (const float*)d_in[9];
    const float* bih1 = (const float*)d_in[10];
    const float* bhh1 = (const float*)d_in[11];
    const float* Wk = (const float*)d_in[12];
    const float* bk = (const float*)d_in[13];
    const float* Wc = (const float*)d_in[14];
    const float* bc = (const float*)d_in[15];
    const float* Wp = (const float*)d_in[16];
    const float* bp = (const float*)d_in[17];
    float* out = (float*)d_out;

    float *pW0, *pW1, *pWkT, *pX0, *pX1, *pXc, *pHB, *pG0, *pG1, *pQ, *pGc;
    cudaGetSymbolAddress((void**)&pW0, dW0);
    cudaGetSymbolAddress((void**)&pW1, dW1);
    cudaGetSymbolAddress((void**)&pWkT, dWkT);
    cudaGetSymbolAddress((void**)&pX0, dX0);
    cudaGetSymbolAddress((void**)&pX1, dX1);
    cudaGetSymbolAddress((void**)&pXc, dXc);
    cudaGetSymbolAddress((void**)&pHB, dHB);
    cudaGetSymbolAddress((void**)&pG0, dG0);
    cudaGetSymbolAddress((void**)&pG1, dG1);
    cudaGetSymbolAddress((void**)&pQ, dQ);
    cudaGetSymbolAddress((void**)&pGc, dGc);

    pk_w0<<<2048, 256>>>(Wih0, Whh0);
    pk_w1<<<2048, 256>>>(Wih1, Whh1);
    pk_wp<<<2048, 256>>>(Wp);
    pk_misc<<<2048, 256>>>(Wk, bih0, bhh0, bih1, bhh1, h0, c0, Eb, tok);

    for (int t = 0; t < T_; t++) {
        gemm_step<<<dim3(64, 2), 256>>>(pW0, pX0, pG0, K0_);
        pw0<<<128, 256>>>();
        gemm_step<<<dim3(64, 2), 256>>>(pW1, pX1, pG1, K1_);
        pw1<<<128, 256>>>(t);
        gemm_step<<<dim3(16, 1), 256>>>(pWkT, pHB + (size_t)t * B_ * H_, pQ, H_);
        attn<<<32, 256>>>(t, tok, bk);
        gemm_step<<<dim3(16, 2), 256>>>(Wc, pXc, pGc, K1_);
        store_comb<<<128, 256>>>(t, bc, Eb, tok);
    }

    gemm_logits<<<dim3(V_ / 64, (T_ * B_) / 64), 256>>>(bp);
    softmax_out<<<T_ * B_, 256>>>(out);
    fixup<<<T_ * B_, 64>>>(out, tok);
}

// round 6
// speedup vs baseline: 2.5652x; 2.5652x over previous
#include <cuda_runtime.h>
#include <cuda_bf16.h>
#include <stdint.h>
#include <math.h>

#define T_ 64
#define B_ 32
#define V_ 32000
#define H_ 1024
#define K0_ 2560
#define K1_ 2048
#define NBLK 128

// ---------------- device scratch ----------------
__device__ __nv_bfloat16 dW0i[(size_t)4096 * K0_];   // gate-interleaved rows
__device__ __nv_bfloat16 dW1i[(size_t)4096 * K1_];
__device__ __nv_bfloat16 dWkT[(size_t)H_ * H_];
__device__ __nv_bfloat16 dWc[(size_t)H_ * K1_];
__device__ __nv_bfloat16 dWp[(size_t)V_ * H_];
__device__ float dB0[4096], dB1[4096];               // gate-interleaved biases
__device__ __nv_bfloat16 dX0bf[B_ * K0_];            // [emb|feed|h0]
__device__ __nv_bfloat16 dX1bf[B_ * K1_];            // [h0_new|h1_prev]
__device__ __nv_bfloat16 dXcbf[B_ * K1_];            // [htop|summary]
__device__ __nv_bfloat16 dH0s[B_ * H_], dH1s[B_ * H_];
__device__ float dC0[B_ * H_], dC1[B_ * H_];         // [h][b]
__device__ float dQ[H_ * B_];                        // [h][b]
__device__ float dHB[(size_t)T_ * B_ * H_];
__device__ float dDist[T_ * T_ * B_];
__device__ __nv_bfloat16 dA[(size_t)T_ * B_ * H_];
__device__ float dMx[T_ * B_], dIs[T_ * B_], dCw[T_ * B_];
__device__ float dLog[(size_t)T_ * B_ * V_];
__device__ volatile int gArr[NBLK];
__device__ volatile int gRel;

__device__ __forceinline__ float sigf(float x) { return 1.0f / (1.0f + expf(-x)); }

__device__ __forceinline__ float ldcgf(const float* p) {
    float v; asm volatile("ld.global.cg.f32 %0,[%1];" : "=f"(v) : "l"(p)); return v;
}
__device__ __forceinline__ float4 ldcgf4(const float* p) {
    float4 v;
    asm volatile("ld.global.cg.v4.f32 {%0,%1,%2,%3},[%4];"
                 : "=f"(v.x), "=f"(v.y), "=f"(v.z), "=f"(v.w) : "l"(p));
    return v;
}
__device__ __forceinline__ unsigned ldcgu(const void* p) {
    unsigned v; asm volatile("ld.global.cg.b32 %0,[%1];" : "=r"(v) : "l"(p)); return v;
}
__device__ __forceinline__ __nv_bfloat16 ldcgbf(const __nv_bfloat16* p) {
    unsigned short v; asm volatile("ld.global.cg.u16 %0,[%1];" : "=h"(v) : "l"(p));
    return *reinterpret_cast<__nv_bfloat16*>(&v);
}
__device__ __forceinline__ void mma16(float c[4], unsigned a0, unsigned a1,
                                      unsigned a2, unsigned a3, unsigned b0, unsigned b1) {
    asm volatile("mma.sync.aligned.m16n8k16.row.col.f32.bf16.bf16.f32 "
                 "{%0,%1,%2,%3},{%4,%5,%6,%7},{%8,%9},{%0,%1,%2,%3};"
                 : "+f"(c[0]), "+f"(c[1]), "+f"(c[2]), "+f"(c[3])
                 : "r"(a0), "r"(a1), "r"(a2), "r"(a3), "r"(b0), "r"(b1));
}

// ---------------- grid barrier (flags, no atomics) ----------------
__device__ __forceinline__ void gbar(int e) {
    __syncthreads();
    if (threadIdx.x == 0) { __threadfence(); gArr[blockIdx.x] = e; }
    if (blockIdx.x == 0) {
        if (threadIdx.x < NBLK) while (gArr[threadIdx.x] < e) { }
        __syncthreads();
        if (threadIdx.x == 0) { __threadfence(); gRel = e; }
    } else {
        if (threadIdx.x == 0) while (gRel < e) { }
    }
    __syncthreads();
}

// ---------------- 32x32 GEMM tile, bf16 mma, K split over 2 warp-groups ----------------
// Out G[kseg][j(32)][b(32)] fp32 in smem; W const (L1 ok), X via .cg (cross-block).
template <int KH, int LDW, int LDX>
__device__ __forceinline__ void gemm_tile(const __nv_bfloat16* __restrict__ W,
                                          const __nv_bfloat16* __restrict__ X,
                                          int j0, float (*G)[32][33]) {
    int tid = threadIdx.x, wid = tid >> 5, lane = tid & 31;
    int ks = wid >> 2, mh = (wid >> 1) & 1, nh = wid & 1;
    int r = lane >> 2, c2 = (lane & 3) * 2;
    const __nv_bfloat16* Wr = W + (size_t)(j0 + mh * 16 + r) * LDW + ks * KH;
    const __nv_bfloat16* Xr = X + (size_t)(nh * 16 + r) * LDX + ks * KH;
    float c0[4] = {0, 0, 0, 0}, c1[4] = {0, 0, 0, 0};
#pragma unroll 4
    for (int kk = 0; kk < KH; kk += 16) {
        unsigned a0 = *(const unsigned*)(Wr + kk + c2);
        unsigned a1 = *(const unsigned*)(Wr + 8 * LDW + kk + c2);
        unsigned a2 = *(const unsigned*)(Wr + kk + c2 + 8);
        unsigned a3 = *(const unsigned*)(Wr + 8 * LDW + kk + c2 + 8);
        unsigned b00 = ldcgu(Xr + kk + c2);
        unsigned b01 = ldcgu(Xr + kk + c2 + 8);
        unsigned b10 = ldcgu(Xr + 8 * LDX + kk + c2);
        unsigned b11 = ldcgu(Xr + 8 * LDX + kk + c2 + 8);
        mma16(c0, a0, a1, a2, a3, b00, b01);
        mma16(c1, a0, a1, a2, a3, b10, b11);
    }
    int row = mh * 16 + r, col = nh * 16 + c2;
    G[ks][row][col] = c0[0];     G[ks][row][col + 1] = c0[1];
    G[ks][row + 8][col] = c0[2]; G[ks][row + 8][col + 1] = c0[3];
    G[ks][row][col + 8] = c1[0];     G[ks][row][col + 9] = c1[1];
    G[ks][row + 8][col + 8] = c1[2]; G[ks][row + 8][col + 9] = c1[3];
}

// ---------------- attention (one block per b) ----------------
__device__ void attention(int t, int b, const int* __restrict__ tok,
                          const float* __restrict__ bk, float* sraw) {
    float* qv = sraw;            // 1024
    float* sc = sraw + 1024;     // 64
    float* red = sraw + 1088;    // 256
    int tid = threadIdx.x;
    int h4 = tid * 4;
    {
        float4 q;
        q.x = ldcgf(&dQ[(h4 + 0) * 32 + b]);
        q.y = ldcgf(&dQ[(h4 + 1) * 32 + b]);
        q.z = ldcgf(&dQ[(h4 + 2) * 32 + b]);
        q.w = ldcgf(&dQ[(h4 + 3) * 32 + b]);
        *(float4*)&qv[h4] = q;
        float4 hv = ldcgf4(&dHB[((size_t)t * 32 + b) * H_ + h4]);
        float4 bv = *(const float4*)&bk[h4];
        red[tid] = hv.x * bv.x + hv.y * bv.y + hv.z * bv.z + hv.w * bv.w;
    }
    __syncthreads();
    for (int st = 128; st; st >>= 1) { if (tid < st) red[tid] += red[tid + st]; __syncthreads(); }
    float bkh = red[0];
    __syncthreads();
    int w = tid >> 5, lane = tid & 31;
    for (int si = w; si <= t; si += 8) {
        const float* hr = &dHB[((size_t)si * 32 + b) * H_];
        float acc = 0.f;
        for (int h = lane * 4; h < H_; h += 128) {
            float4 hv = ldcgf4(hr + h);
            float4 qq = *(float4*)&qv[h];
            acc += hv.x * qq.x + hv.y * qq.y + hv.z * qq.z + hv.w * qq.w;
        }
#pragma unroll
        for (int o = 16; o; o >>= 1) acc += __shfl_xor_sync(0xffffffffu, acc, o);
        if (!lane) {
            float v = acc + bkh;
            if (tok[si * 32 + b] == 0) v += -99999.0f;
            sc[si] = v;
        }
    }
    __syncthreads();
    if (tid == 0) {
        float m = -1e30f;
        for (int s2 = 0; s2 <= t; s2++) m = fmaxf(m, sc[s2]);
        float sum = 0.f;
        for (int s2 = 0; s2 <= t; s2++) { float e2 = expf(sc[s2] - m); sc[s2] = e2; sum += e2; }
        float inv = 1.0f / sum;
        for (int s2 = 0; s2 <= t; s2++) sc[s2] *= inv;
    }
    __syncthreads();
    for (int s2 = tid; s2 < T_; s2 += 256)
        dDist[(t * T_ + s2) * 32 + b] = (s2 <= t) ? sc[s2] : 0.0f;
    {
        float4 a = {0, 0, 0, 0};
        for (int s2 = 0; s2 <= t; s2++) {
            float4 hv = ldcgf4(&dHB[((size_t)s2 * 32 + b) * H_ + h4]);
            float d = sc[s2];
            a.x += d * hv.x; a.y += d * hv.y; a.z += d * hv.z; a.w += d * hv.w;
        }
        __nv_bfloat16* o = &dXcbf[b * K1_ + 1024 + h4];
        o[0] = __float2bfloat16(a.x); o[1] = __float2bfloat16(a.y);
        o[2] = __float2bfloat16(a.z); o[3] = __float2bfloat16(a.w);
    }
}

// ---------------- persistent decode loop ----------------
__global__ void __launch_bounds__(256, 1)
decode_loop(const int* __restrict__ tok, const float* __restrict__ Eb,
            const float* __restrict__ bk, const float* __restrict__ bc) {
    __shared__ __align__(16) float sraw[2 * 32 * 33];
    float (*G)[32][33] = (float(*)[32][33])sraw;
    int bid = blockIdx.x, tid = threadIdx.x;
    int b = tid & 31, hl = tid >> 5;
    int e = 0;

    for (int t = 0; t < T_; t++) {
        // ---- Phase A: layer-0 GEMM + LSTM pointwise (gate-interleaved) ----
        gemm_tile<K0_ / 2, K0_, K0_>(dW0i, dX0bf, bid * 32, G);
        __syncthreads();
        {
            int j0 = bid * 32;
            float gi = G[0][hl * 4 + 0][b] + G[1][hl * 4 + 0][b] + dB0[j0 + hl * 4 + 0];
            float gf = G[0][hl * 4 + 1][b] + G[1][hl * 4 + 1][b] + dB0[j0 + hl * 4 + 1];
            float gg = G[0][hl * 4 + 2][b] + G[1][hl * 4 + 2][b] + dB0[j0 + hl * 4 + 2];
            float go = G[0][hl * 4 + 3][b] + G[1][hl * 4 + 3][b] + dB0[j0 + hl * 4 + 3];
            int h = bid * 8 + hl;
            float c = ldcgf(&dC0[h * 32 + b]);
            float cn = sigf(gf) * c + sigf(gi) * tanhf(gg);
            float hn = sigf(go) * tanhf(cn);
            dC0[h * 32 + b] = cn;
            __nv_bfloat16 hb = __float2bfloat16(hn);
            dX1bf[b * K1_ + h] = hb;
            dH0s[b * H_ + h] = hb;
        }
        gbar(++e);

        // ---- Phase B: layer-1 GEMM + LSTM pointwise ----
        gemm_tile<K1_ / 2, K1_, K1_>(dW1i, dX1bf, bid * 32, G);
        __syncthreads();
        {
            int j0 = bid * 32;
            float gi = G[0][hl * 4 + 0][b] + G[1][hl * 4 + 0][b] + dB1[j0 + hl * 4 + 0];
            float gf = G[0][hl * 4 + 1][b] + G[1][hl * 4 + 1][b] + dB1[j0 + hl * 4 + 1];
            float gg = G[0][hl * 4 + 2][b] + G[1][hl * 4 + 2][b] + dB1[j0 + hl * 4 + 2];
            float go = G[0][hl * 4 + 3][b] + G[1][hl * 4 + 3][b] + dB1[j0 + hl * 4 + 3];
            int h = bid * 8 + hl;
            float c = ldcgf(&dC1[h * 32 + b]);
            float cn = sigf(gf) * c + sigf(gi) * tanhf(gg);
            float hn = sigf(go) * tanhf(cn);
            dC1[h * 32 + b] = cn;
            __nv_bfloat16 hb = __float2bfloat16(hn);
            dH1s[b * H_ + h] = hb;
            dXcbf[b * K1_ + h] = hb;                       // htop (E, C input)
            dHB[((size_t)t * 32 + b) * H_ + h] = hn;       // fp32 for attention
        }
        gbar(++e);

        // ---- Phase C: q-GEMM + state copies + emb prefetch ----
        if (bid < 32) {
            gemm_tile<H_ / 2, H_, K1_>(dWkT, dXcbf, bid * 32, G);
            __syncthreads();
#pragma unroll
            for (int r2 = 0; r2 < 4; r2++) {
                int jl = hl + r2 * 8;
                dQ[(bid * 32 + jl) * 32 + b] = G[0][jl][b] + G[1][jl][b];
            }
        } else if (bid < 64) {
            int bb = bid - 32;
            for (int h = tid; h < H_; h += 256)
                dX0bf[bb * K0_ + 1536 + h] = ldcgbf(&dH0s[bb * H_ + h]);
        } else if (bid < 96) {
            int bb = bid - 64;
            for (int h = tid; h < H_; h += 256)
                dX1bf[bb * K1_ + 1024 + h] = ldcgbf(&dH1s[bb * H_ + h]);
        } else if (t + 1 < T_) {
            int bb = bid - 96;
            int tk = tok[(t + 1) * 32 + bb];
            for (int e2 = tid; e2 < 512; e2 += 256)
                dX0bf[bb * K0_ + e2] = __float2bfloat16(Eb[(size_t)tk * 512 + e2]);
        }
        gbar(++e);

        // ---- Phase D: attention ----
        if (bid < 32) attention(t, bid, tok, bk, sraw);
        gbar(++e);

        // ---- Phase E: comb GEMM + feed/A write ----
        if (bid < 32) {
            gemm_tile<K1_ / 2, K1_, K1_>(dWc, dXcbf, bid * 32, G);
            __syncthreads();
#pragma unroll
            for (int r2 = 0; r2 < 4; r2++) {
                int jl = hl + r2 * 8;
                int j = bid * 32 + jl;
                float v = G[0][jl][b] + G[1][jl][b] + bc[j];
                __nv_bfloat16 vb = __float2bfloat16(v);
                dX0bf[b * K0_ + 512 + j] = vb;
                dA[((size_t)t * 32 + b) * H_ + j] = vb;
            }
        }
        gbar(++e);
    }
}

// ---------------- prep kernels ----------------
__global__ void pk_w0i(const float* __restrict__ Wih, const float* __restrict__ Whh) {
    for (size_t i = (size_t)blockIdx.x * blockDim.x + threadIdx.x; i < (size_t)4096 * K0_;
         i += (size_t)gridDim.x * blockDim.x) {
        size_t jp = i / K0_, k = i % K0_;
        size_t h = jp >> 2, g = jp & 3, orig = g * 1024 + h;
        float v = (k < 1536) ? Wih[orig * 1536 + k] : Whh[orig * 1024 + (k - 1536)];
        dW0i[i] = __float2bfloat16(v);
    }
}
__global__ void pk_w1i(const float* __restrict__ Wih, const float* __restrict__ Whh) {
    for (size_t i = (size_t)blockIdx.x * blockDim.x + threadIdx.x; i < (size_t)4096 * K1_;
         i += (size_t)gridDim.x * blockDim.x) {
        size_t jp = i / K1_, k = i % K1_;
        size_t h = jp >> 2, g = jp & 3, orig = g * 1024 + h;
        float v = (k < 1024) ? Wih[orig * 1024 + k] : Whh[orig * 1024 + (k - 1024)];
        dW1i[i] = __float2bfloat16(v);
    }
}
__global__ void pk_wkc(const float* __restrict__ Wk, const float* __restrict__ Wc) {
    for (size_t i = (size_t)blockIdx.x * blockDim.x + threadIdx.x; i < (size_t)H_ * K1_;
         i += (size_t)gridDim.x * blockDim.x) {
        dWc[i] = __float2bfloat16(Wc[i]);
        if (i < (size_t)H_ * H_) {
            size_t r = i >> 10, c = i & 1023;
            dWkT[i] = __float2bfloat16(Wk[c * 1024 + r]);
        }
    }
}
__global__ void pk_wp(const float* __restrict__ Wp) {
    for (size_t i = (size_t)blockIdx.x * blockDim.x + threadIdx.x; i < (size_t)V_ * H_;
         i += (size_t)gridDim.x * blockDim.x)
        dWp[i] = __float2bfloat16(Wp[i]);
}
__global__ void pk_state(const float* __restrict__ bih0, const float* __restrict__ bhh0,
                         const float* __restrict__ bih1, const float* __restrict__ bhh1,
                         const float* __restrict__ h0, const float* __restrict__ c0,
                         const float* __restrict__ Eb, const int* __restrict__ tok) {
    int i = blockIdx.x * blockDim.x + threadIdx.x;   // 32768 threads
    int bb = i / 1024, h = i % 1024;
    dC0[h * 32 + bb] = c0[(size_t)bb * H_ + h];
    dC1[h * 32 + bb] = c0[(size_t)B_ * H_ + (size_t)bb * H_ + h];
    dX0bf[bb * K0_ + 1536 + h] = __float2bfloat16(h0[(size_t)bb * H_ + h]);
    dX1bf[bb * K1_ + 1024 + h] = __float2bfloat16(h0[(size_t)B_ * H_ + (size_t)bb * H_ + h]);
    dX0bf[bb * K0_ + 512 + h] = __float2bfloat16(0.0f);
    if (i < 4096) {
        int h2 = i >> 2, g = i & 3;
        dB0[i] = bih0[g * 1024 + h2] + bhh0[g * 1024 + h2];
        dB1[i] = bih1[g * 1024 + h2] + bhh1[g * 1024 + h2];
    }
    if (i < 32 * 512) {
        int b2 = i / 512, e2 = i % 512;
        dX0bf[b2 * K0_ + e2] = __float2bfloat16(Eb[(size_t)tok[b2] * 512 + e2]);
    }
    if (i < NBLK) gArr[i] = 0;
    if (i == 0) gRel = 0;
}

// ---------------- logits GEMM: 128x128 double-buffered bf16 ----------------
__global__ void __launch_bounds__(256) gemm_logits(const float* __restrict__ bp) {
    int v0 = blockIdx.x * 128, r0 = blockIdx.y * 128;
    __shared__ __nv_bfloat16 As[2][128][16];
    __shared__ __nv_bfloat16 Bs[2][128][16];
    int tid = threadIdx.x, wid = tid >> 5, lane = tid & 31;
    int mh = wid >> 2, nq = wid & 3;
    int r = lane >> 2, c2 = (lane & 3) * 2;
    int lrow = tid >> 1, lseg = (tid & 1) * 8;
    float acc[4][4][4];
#pragma unroll
    for (int a = 0; a < 4; a++)
#pragma unroll
        for (int bb = 0; bb < 4; bb++)
#pragma unroll
            for (int c = 0; c < 4; c++) acc[a][bb][c] = 0.f;

    *(uint4*)&As[0][lrow][lseg] = *(const uint4*)&dA[(size_t)(r0 + lrow) * H_ + lseg];
    *(uint4*)&Bs[0][lrow][lseg] = *(const uint4*)&dWp[(size_t)(v0 + lrow) * H_ + lseg];
    __syncthreads();
    for (int ks = 0; ks < 64; ks++) {
        uint4 na, nb;
        if (ks < 63) {
            na = *(const uint4*)&dA[(size_t)(r0 + lrow) * H_ + (ks + 1) * 16 + lseg];
            nb = *(const uint4*)&dWp[(size_t)(v0 + lrow) * H_ + (ks + 1) * 16 + lseg];
        }
        int cur = ks & 1;
#pragma unroll
        for (int mi = 0; mi < 4; mi++) {
            int row = mh * 64 + mi * 16;
            unsigned a0 = *(unsigned*)&As[cur][row + r][c2];
            unsigned a1 = *(unsigned*)&As[cur][row + r + 8][c2];
            unsigned a2 = *(unsigned*)&As[cur][row + r][c2 + 8];
            unsigned a3 = *(unsigned*)&As[cur][row + r + 8][c2 + 8];
#pragma unroll
            for (int ni = 0; ni < 4; ni++) {
                int n = nq * 32 + ni * 8 + r;
                unsigned b0 = *(unsigned*)&Bs[cur][n][c2];
                unsigned b1 = *(unsigned*)&Bs[cur][n][c2 + 8];
                mma16(acc[mi][ni], a0, a1, a2, a3, b0, b1);
            }
        }
        __syncthreads();
        if (ks < 63) {
            *(uint4*)&As[cur ^ 1][lrow][lseg] = na;
            *(uint4*)&Bs[cur ^ 1][lrow][lseg] = nb;
        }
        __syncthreads();
    }
#pragma unroll
    for (int mi = 0; mi < 4; mi++) {
        int row = r0 + mh * 64 + mi * 16 + r;
#pragma unroll
        for (int ni = 0; ni < 4; ni++) {
            int col = v0 + nq * 32 + ni * 8 + c2;
            float b0 = bp[col], b1 = bp[col + 1];
            dLog[(size_t)row * V_ + col] = acc[mi][ni][0] + b0;
            dLog[(size_t)row * V_ + col + 1] = acc[mi][ni][1] + b1;
            dLog[(size_t)(row + 8) * V_ + col] = acc[mi][ni][2] + b0;
            dLog[(size_t)(row + 8) * V_ + col + 1] = acc[mi][ni][3] + b1;
        }
    }
}

// ---------------- softmax + mixture log output (validated round 5) ----------------
__global__ void softmax_out(float* __restrict__ out) {
    int rr = blockIdx.x, tid = threadIdx.x;
    const float* L = dLog + (size_t)rr * V_;
    __shared__ float red[256];
    float m = -1e30f;
    for (int v = tid; v < V_; v += 256) m = fmaxf(m, L[v]);
    red[tid] = m; __syncthreads();
    for (int st = 128; st; st >>= 1) { if (tid < st) red[tid] = fmaxf(red[tid], red[tid + st]); __syncthreads(); }
    m = red[0]; __syncthreads();
    float s = 0.f;
    for (int v = tid; v < V_; v += 256) s += __expf(L[v] - m);
    red[tid] = s; __syncthreads();
    for (int st = 128; st; st >>= 1) { if (tid < st) red[tid] += red[tid + st]; __syncthreads(); }
    s = red[0];
    float inv = 1.0f / s;
    float cw = __expf(L[3] - m) * inv;
    if (tid == 0) { dMx[rr] = m; dIs[rr] = inv; dCw[rr] = cw; }
    float ce = cw * 1e-7f, oc = 1.0f - cw;
    float* O = out + (size_t)rr * V_;
    for (int v = tid; v < V_; v += 256)
        O[v] = __logf(ce + oc * __expf(L[v] - m) * inv);
}

__global__ void fixup(float* __restrict__ out, const int* __restrict__ tok) {
    int rr = blockIdx.x;
    int t = rr >> 5, b = rr & 31;
    int s = threadIdx.x;
    __shared__ int tk[T_];
    __shared__ float dd[T_];
    tk[s] = tok[s * 32 + b];
    dd[s] = dDist[(t * T_ + s) * 32 + b];
    __syncthreads();
    int mytok = tk[s];
    float tot = 0.f;
    for (int s2 = 0; s2 < T_; s2++) if (tk[s2] == mytok) tot += dd[s2];
    float m = dMx[rr], inv = dIs[rr], cw = dCw[rr];
    float p = __expf(dLog[(size_t)rr * V_ + mytok] - m) * inv;
    out[(size_t)rr * V_ + mytok] = __logf(cw * (1e-7f + tot) + (1.0f - cw) * p);
}

// ---------------- host ----------------
extern "C" void kernel_launch(void* const* d_in, const int* in_sizes, int n_in,
                              void* d_out, int out_size) {
    const int* tok = (const int*)d_in[0];
    const float* h0 = (const float*)d_in[1];
    const float* c0 = (const float*)d_in[2];
    const float* Eb = (const float*)d_in[3];
    const float* Wih0 = (const float*)d_in[4];
    const float* Whh0 = (const float*)d_in[5];
    const float* bih0 = (const float*)d_in[6];
    const float* bhh0 = (const float*)d_in[7];
    const float* Wih1 = (const float*)d_in[8];
    const float* Whh1 = (const float*)d_in[9];
    const float* bih1 = (const float*)d_in[10];
    const float* bhh1 = (const float*)d_in[11];
    const float* Wk = (const float*)d_in[12];
    const float* bk = (const float*)d_in[13];
    const float* Wc = (const float*)d_in[14];
    const float* bc = (const float*)d_in[15];
    const float* Wp = (const float*)d_in[16];
    const float* bp = (const float*)d_in[17];
    float* out = (float*)d_out;

    pk_w0i<<<2048, 256>>>(Wih0, Whh0);
    pk_w1i<<<2048, 256>>>(Wih1, Whh1);
    pk_wkc<<<1024, 256>>>(Wk, Wc);
    pk_wp<<<4096, 256>>>(Wp);
    pk_state<<<128, 256>>>(bih0, bhh0, bih1, bhh1, h0, c0, Eb, tok);

    decode_loop<<<NBLK, 256>>>(tok, Eb, bk, bc);

    gemm_logits<<<dim3(V_ / 128, (T_ * B_) / 128), 256>>>(bp);
    softmax_out<<<T_ * B_, 256>>>(out);
    fixup<<<T_ * B_, 64>>>(out, tok);
}

// round 7
// speedup vs baseline: 5.7138x; 2.2274x over previous
#include <cuda_runtime.h>
#include <cuda_bf16.h>
#include <stdint.h>
#include <math.h>

#define T_ 64
#define B_ 32
#define V_ 32000
#define H_ 1024
#define K0_ 2560
#define K1_ 2048
#define NBLK 128

// ---------------- device scratch ----------------
// fragment-packed weights: [jtile][panel(K/16)][mh(2)][lane(32)] uint4
__device__ uint4 dW0p[(size_t)4096 * K0_ / 8];
__device__ uint4 dW1p[(size_t)4096 * K1_ / 8];
__device__ uint4 dWkp[(size_t)H_ * H_ / 8];
__device__ uint4 dWcp[(size_t)H_ * K1_ / 8];
__device__ __nv_bfloat16 dWp[(size_t)V_ * H_];
__device__ float dB0[4096], dB1[4096];
// fragment-packed activations: [panel][nh(2)][lane(32)] uint4
__device__ uint4 dX0p[(K0_ / 16) * 64];
__device__ uint4 dX1p[(K1_ / 16) * 64];
__device__ uint4 dXcp[(K1_ / 16) * 64];
__device__ __nv_bfloat16 dH0s[B_ * H_], dH1s[B_ * H_];
__device__ float dC0[B_ * H_], dC1[B_ * H_];
__device__ float dQ[H_ * B_];
__device__ __nv_bfloat16 dHBh[(size_t)T_ * B_ * H_];
__device__ float dDist[T_ * T_ * B_];
__device__ __nv_bfloat16 dA[(size_t)T_ * B_ * H_];
__device__ float dMx[T_ * B_], dIs[T_ * B_], dCw[T_ * B_];
__device__ float dLog[(size_t)T_ * B_ * V_];
__device__ int gArr[NBLK];
__device__ int gRel;

__device__ __forceinline__ float sigf(float x) { return 1.0f / (1.0f + expf(-x)); }

// packed-X bf16 index for activation value (n=batch, k=feature)
__device__ __forceinline__ int xpk(int n, int k) {
    int p = k >> 4, hi = (k >> 3) & 1, lo = k & 1, ci = (k >> 1) & 3;
    int nh = n >> 4, rh = (n >> 3) & 1, r = n & 7;
    return ((((p * 2 + nh) * 32 + (r * 4 + ci)) * 4) + (rh * 2 + hi)) * 2 + lo;
}

__device__ __forceinline__ float ldcgf(const float* p) {
    float v; asm volatile("ld.global.cg.f32 %0,[%1];" : "=f"(v) : "l"(p)); return v;
}
__device__ __forceinline__ uint2 ldcg2(const void* p) {
    uint2 v; asm volatile("ld.global.cg.v2.b32 {%0,%1},[%2];" : "=r"(v.x), "=r"(v.y) : "l"(p));
    return v;
}
__device__ __forceinline__ uint4 ldcg4(const void* p) {
    uint4 v;
    asm volatile("ld.global.cg.v4.b32 {%0,%1,%2,%3},[%4];"
                 : "=r"(v.x), "=r"(v.y), "=r"(v.z), "=r"(v.w) : "l"(p));
    return v;
}
__device__ __forceinline__ __nv_bfloat16 ldcgbf(const __nv_bfloat16* p) {
    unsigned short v; asm volatile("ld.global.cg.u16 %0,[%1];" : "=h"(v) : "l"(p));
    return *reinterpret_cast<__nv_bfloat16*>(&v);
}
__device__ __forceinline__ void st_rel(int* p, int v) {
    asm volatile("st.release.gpu.global.s32 [%0],%1;" :: "l"(p), "r"(v) : "memory");
}
__device__ __forceinline__ int ld_acq(const int* p) {
    int v; asm volatile("ld.acquire.gpu.global.s32 %0,[%1];" : "=r"(v) : "l"(p) : "memory");
    return v;
}
__device__ __forceinline__ void mma16(float c[4], unsigned a0, unsigned a1,
                                      unsigned a2, unsigned a3, unsigned b0, unsigned b1) {
    asm volatile("mma.sync.aligned.m16n8k16.row.col.f32.bf16.bf16.f32 "
                 "{%0,%1,%2,%3},{%4,%5,%6,%7},{%8,%9},{%0,%1,%2,%3};"
                 : "+f"(c[0]), "+f"(c[1]), "+f"(c[2]), "+f"(c[3])
                 : "r"(a0), "r"(a1), "r"(a2), "r"(a3), "r"(b0), "r"(b1));
}

// ---------------- grid barrier (release/acquire) ----------------
__device__ __forceinline__ void gbar(int e) {
    __syncthreads();
    if (threadIdx.x == 0) st_rel(&gArr[blockIdx.x], e);
    if (blockIdx.x == 0) {
        if (threadIdx.x < NBLK) while (ld_acq(&gArr[threadIdx.x]) < e) { }
        __syncthreads();
        if (threadIdx.x == 0) st_rel(&gRel, e);
    } else if (threadIdx.x == 0) {
        while (ld_acq(&gRel) < e) { }
    }
    __syncthreads();
}

// ---------------- packed 32x32xKC GEMM: 8 k-segment warps ----------------
// Wt: packed tile base for this block's 32 rows. Xp: packed activations.
// G[wid][row][col] partial outputs; caller reduces over 8 segments.
template <int KC>
__device__ __forceinline__ void gemm_p(const uint4* __restrict__ Wt,
                                       const uint4* __restrict__ Xp,
                                       float (*G)[32][33]) {
    int tid = threadIdx.x, wid = tid >> 5, lane = tid & 31;
    constexpr int PPW = KC / 128;   // panels per warp
    const uint4* Wr = Wt + (size_t)(wid * PPW * 2) * 32 + lane;
    const uint4* Xr = Xp + (size_t)(wid * PPW * 2) * 32 + lane;
    float c[2][4][4];
#pragma unroll
    for (int i = 0; i < 2; i++)
#pragma unroll
        for (int j = 0; j < 4; j++)
#pragma unroll
            for (int k = 0; k < 4; k++) c[i][j][k] = 0.f;
#pragma unroll 4
    for (int p = 0; p < PPW; p++) {
        uint4 A0 = Wr[p * 64];
        uint4 A1 = Wr[p * 64 + 32];
        uint4 B0 = ldcg4(Xr + p * 64);
        uint4 B1 = ldcg4(Xr + p * 64 + 32);
        mma16(c[0][0], A0.x, A0.y, A0.z, A0.w, B0.x, B0.y);
        mma16(c[0][1], A0.x, A0.y, A0.z, A0.w, B0.z, B0.w);
        mma16(c[0][2], A0.x, A0.y, A0.z, A0.w, B1.x, B1.y);
        mma16(c[0][3], A0.x, A0.y, A0.z, A0.w, B1.z, B1.w);
        mma16(c[1][0], A1.x, A1.y, A1.z, A1.w, B0.x, B0.y);
        mma16(c[1][1], A1.x, A1.y, A1.z, A1.w, B0.z, B0.w);
        mma16(c[1][2], A1.x, A1.y, A1.z, A1.w, B1.x, B1.y);
        mma16(c[1][3], A1.x, A1.y, A1.z, A1.w, B1.z, B1.w);
    }
    int r = lane >> 2, c2 = (lane & 3) * 2;
#pragma unroll
    for (int mh = 0; mh < 2; mh++)
#pragma unroll
        for (int q = 0; q < 4; q++) {
            int row = mh * 16 + r, col = (q >> 1) * 16 + (q & 1) * 8 + c2;
            G[wid][row][col] = c[mh][q][0];
            G[wid][row][col + 1] = c[mh][q][1];
            G[wid][row + 8][col] = c[mh][q][2];
            G[wid][row + 8][col + 1] = c[mh][q][3];
        }
}

__device__ __forceinline__ float gsum(float (*G)[32][33], int row, int b) {
    float s = 0.f;
#pragma unroll
    for (int k = 0; k < 8; k++) s += G[k][row][b];
    return s;
}

// ---------------- attention (one block per b) ----------------
__device__ void attention(int t, int b, const int* __restrict__ tok,
                          const float* __restrict__ bk, float* sraw) {
    float* qv = sraw;            // 1024
    float* sc = sraw + 1024;     // 64
    float* red = sraw + 1088;    // 256
    int tid = threadIdx.x;
    int h4 = tid * 4;
    {
        qv[h4 + 0] = ldcgf(&dQ[(h4 + 0) * 32 + b]);
        qv[h4 + 1] = ldcgf(&dQ[(h4 + 1) * 32 + b]);
        qv[h4 + 2] = ldcgf(&dQ[(h4 + 2) * 32 + b]);
        qv[h4 + 3] = ldcgf(&dQ[(h4 + 3) * 32 + b]);
        uint2 hv = ldcg2(&dHBh[((size_t)t * 32 + b) * H_ + h4]);
        float2 f0 = __bfloat1622float2(*(__nv_bfloat162*)&hv.x);
        float2 f1 = __bfloat1622float2(*(__nv_bfloat162*)&hv.y);
        float4 bv = *(const float4*)&bk[h4];
        red[tid] = f0.x * bv.x + f0.y * bv.y + f1.x * bv.z + f1.y * bv.w;
    }
    __syncthreads();
    for (int st = 128; st; st >>= 1) { if (tid < st) red[tid] += red[tid + st]; __syncthreads(); }
    float bkh = red[0];
    __syncthreads();
    int w = tid >> 5, lane = tid & 31;
    for (int si = w; si <= t; si += 8) {
        const __nv_bfloat16* hr = &dHBh[((size_t)si * 32 + b) * H_];
        float acc = 0.f;
        for (int h = lane * 8; h < H_; h += 256) {
            uint4 hv = ldcg4(hr + h);
            float2 a0 = __bfloat1622float2(*(__nv_bfloat162*)&hv.x);
            float2 a1 = __bfloat1622float2(*(__nv_bfloat162*)&hv.y);
            float2 a2 = __bfloat1622float2(*(__nv_bfloat162*)&hv.z);
            float2 a3 = __bfloat1622float2(*(__nv_bfloat162*)&hv.w);
            acc += a0.x * qv[h] + a0.y * qv[h + 1] + a1.x * qv[h + 2] + a1.y * qv[h + 3]
                 + a2.x * qv[h + 4] + a2.y * qv[h + 5] + a3.x * qv[h + 6] + a3.y * qv[h + 7];
        }
#pragma unroll
        for (int o = 16; o; o >>= 1) acc += __shfl_xor_sync(0xffffffffu, acc, o);
        if (!lane) {
            float v = acc + bkh;
            if (tok[si * 32 + b] == 0) v += -99999.0f;
            sc[si] = v;
        }
    }
    __syncthreads();
    if (tid == 0) {
        float m = -1e30f;
        for (int s = 0; s <= t; s++) m = fmaxf(m, sc[s]);
        float sum = 0.f;
        for (int s = 0; s <= t; s++) { float e2 = expf(sc[s] - m); sc[s] = e2; sum += e2; }
        float inv = 1.0f / sum;
        for (int s = 0; s <= t; s++) sc[s] *= inv;
    }
    __syncthreads();
    for (int s = tid; s < T_; s += 256)
        dDist[(t * T_ + s) * 32 + b] = (s <= t) ? sc[s] : 0.0f;
    {
        float a0 = 0, a1 = 0, a2 = 0, a3 = 0;
        for (int s = 0; s <= t; s++) {
            uint2 hv = ldcg2(&dHBh[((size_t)s * 32 + b) * H_ + h4]);
            float2 f0 = __bfloat1622float2(*(__nv_bfloat162*)&hv.x);
            float2 f1 = __bfloat1622float2(*(__nv_bfloat162*)&hv.y);
            float d = sc[s];
            a0 += d * f0.x; a1 += d * f0.y; a2 += d * f1.x; a3 += d * f1.y;
        }
        __nv_bfloat162 p0 = __floats2bfloat162_rn(a0, a1);
        __nv_bfloat162 p1 = __floats2bfloat162_rn(a2, a3);
        ((unsigned*)dXcp)[xpk(b, 1024 + h4) >> 1] = *(unsigned*)&p0;
        ((unsigned*)dXcp)[xpk(b, 1024 + h4 + 2) >> 1] = *(unsigned*)&p1;
    }
}

// ---------------- persistent decode loop ----------------
__global__ void __launch_bounds__(256, 1)
decode_loop(const int* __restrict__ tok, const float* __restrict__ Eb,
            const float* __restrict__ bk, const float* __restrict__ bc) {
    __shared__ __align__(16) float Gs[8][32][33];
    int bid = blockIdx.x, tid = threadIdx.x;
    int b = tid & 31, hl = tid >> 5;
    int e = 0;
    const uint4* W0t = dW0p + (size_t)bid * (160 * 64);
    const uint4* W1t = dW1p + (size_t)bid * (128 * 64);

    for (int t = 0; t < T_; t++) {
        // ---- Phase A: layer-0 GEMM + LSTM pointwise ----
        gemm_p<K0_>(W0t, dX0p, Gs);
        __syncthreads();
        {
            int h = bid * 8 + hl, j0 = bid * 32 + hl * 4;
            float g0 = gsum(Gs, hl * 4 + 0, b) + dB0[j0 + 0];
            float g1 = gsum(Gs, hl * 4 + 1, b) + dB0[j0 + 1];
            float g2 = gsum(Gs, hl * 4 + 2, b) + dB0[j0 + 2];
            float g3 = gsum(Gs, hl * 4 + 3, b) + dB0[j0 + 3];
            float c = dC0[h * 32 + b];
            float cn = sigf(g1) * c + sigf(g0) * tanhf(g2);
            float hn = sigf(g3) * tanhf(cn);
            dC0[h * 32 + b] = cn;
            __nv_bfloat16 hb = __float2bfloat16(hn);
            ((__nv_bfloat16*)dX1p)[xpk(b, h)] = hb;   // layer-1 input (this step)
            dH0s[b * H_ + h] = hb;                    // staged for next-step X0
        }
        gbar(++e);

        // ---- Phase B: layer-1 GEMM + LSTM pointwise ----
        gemm_p<K1_>(W1t, dX1p, Gs);
        __syncthreads();
        {
            int h = bid * 8 + hl, j0 = bid * 32 + hl * 4;
            float g0 = gsum(Gs, hl * 4 + 0, b) + dB1[j0 + 0];
            float g1 = gsum(Gs, hl * 4 + 1, b) + dB1[j0 + 1];
            float g2 = gsum(Gs, hl * 4 + 2, b) + dB1[j0 + 2];
            float g3 = gsum(Gs, hl * 4 + 3, b) + dB1[j0 + 3];
            float c = dC1[h * 32 + b];
            float cn = sigf(g1) * c + sigf(g0) * tanhf(g2);
            float hn = sigf(g3) * tanhf(cn);
            dC1[h * 32 + b] = cn;
            __nv_bfloat16 hb = __float2bfloat16(hn);
            ((__nv_bfloat16*)dXcp)[xpk(b, h)] = hb;          // htop
            dH1s[b * H_ + h] = hb;                           // staged for next-step X1
            dHBh[((size_t)t * 32 + b) * H_ + h] = hb;        // hbuf (bf16)
        }
        gbar(++e);

        // ---- Phase C: q-GEMM + state copies + emb prefetch ----
        if (bid < 32) {
            gemm_p<H_>(dWkp + (size_t)bid * (64 * 64), dXcp, Gs);
            __syncthreads();
#pragma unroll
            for (int g = 0; g < 4; g++) {
                int row = hl * 4 + g;
                dQ[(bid * 32 + row) * 32 + b] = gsum(Gs, row, b);
            }
        } else if (bid < 64) {
            int bb = bid - 32;
            for (int h = tid; h < H_; h += 256)
                ((__nv_bfloat16*)dX0p)[xpk(bb, 1536 + h)] = ldcgbf(&dH0s[bb * H_ + h]);
        } else if (bid < 96) {
            int bb = bid - 64;
            for (int h = tid; h < H_; h += 256)
                ((__nv_bfloat16*)dX1p)[xpk(bb, 1024 + h)] = ldcgbf(&dH1s[bb * H_ + h]);
        } else if (t + 1 < T_) {
            int bb = bid - 96;
            int tk = tok[(t + 1) * 32 + bb];
            for (int e2 = tid; e2 < 512; e2 += 256)
                ((__nv_bfloat16*)dX0p)[xpk(bb, e2)] = __float2bfloat16(Eb[(size_t)tk * 512 + e2]);
        }
        gbar(++e);

        // ---- Phase D: attention ----
        if (bid < 32) attention(t, bid, tok, bk, (float*)Gs);
        gbar(++e);

        // ---- Phase E: comb GEMM + feed/A write ----
        if (bid < 32) {
            gemm_p<K1_>(dWcp + (size_t)bid * (128 * 64), dXcp, Gs);
            __syncthreads();
#pragma unroll
            for (int g = 0; g < 4; g++) {
                int row = hl * 4 + g, j = bid * 32 + row;
                float v = gsum(Gs, row, b) + bc[j];
                __nv_bfloat16 vb = __float2bfloat16(v);
                ((__nv_bfloat16*)dX0p)[xpk(b, 512 + j)] = vb;
                dA[((size_t)t * 32 + b) * H_ + j] = vb;
            }
        }
        gbar(++e);
    }
}

// ---------------- weight pack kernels ----------------
__global__ void pk_w0p(const float* __restrict__ Wih, const float* __restrict__ Whh) {
    const size_t N = (size_t)4096 * K0_ / 8;
    for (size_t u = (size_t)blockIdx.x * blockDim.x + threadIdx.x; u < N;
         u += (size_t)gridDim.x * blockDim.x) {
        int lane = (int)(u & 31); size_t t1 = u >> 5; int mh = (int)(t1 & 1); size_t t2 = t1 >> 1;
        int p = (int)(t2 % 160); int jt = (int)(t2 / 160);
        int r = lane >> 2, ci = lane & 3;
        unsigned o[4];
#pragma unroll
        for (int reg = 0; reg < 4; reg++) {
            int rh = reg & 1, hi = reg >> 1;
            int row = jt * 32 + mh * 16 + rh * 8 + r;
            int orow = (row & 3) * 1024 + (row >> 2);   // gate-interleave
            int col = p * 16 + hi * 8 + ci * 2;
            float v0, v1;
            if (col < 1536) { v0 = Wih[(size_t)orow * 1536 + col]; v1 = Wih[(size_t)orow * 1536 + col + 1]; }
            else { v0 = Whh[(size_t)orow * 1024 + col - 1536]; v1 = Whh[(size_t)orow * 1024 + col - 1535]; }
            __nv_bfloat162 bb = __floats2bfloat162_rn(v0, v1);
            o[reg] = *(unsigned*)&bb;
        }
        dW0p[u] = make_uint4(o[0], o[1], o[2], o[3]);
    }
}
__global__ void pk_w1p(const float* __restrict__ Wih, const float* __restrict__ Whh) {
    const size_t N = (size_t)4096 * K1_ / 8;
    for (size_t u = (size_t)blockIdx.x * blockDim.x + threadIdx.x; u < N;
         u += (size_t)gridDim.x * blockDim.x) {
        int lane = (int)(u & 31); size_t t1 = u >> 5; int mh = (int)(t1 & 1); size_t t2 = t1 >> 1;
        int p = (int)(t2 % 128); int jt = (int)(t2 / 128);
        int r = lane >> 2, ci = lane & 3;
        unsigned o[4];
#pragma unroll
        for (int reg = 0; reg < 4; reg++) {
            int rh = reg & 1, hi = reg >> 1;
            int row = jt * 32 + mh * 16 + rh * 8 + r;
            int orow = (row & 3) * 1024 + (row >> 2);
            int col = p * 16 + hi * 8 + ci * 2;
            float v0, v1;
            if (col < 1024) { v0 = Wih[(size_t)orow * 1024 + col]; v1 = Wih[(size_t)orow * 1024 + col + 1]; }
            else { v0 = Whh[(size_t)orow * 1024 + col - 1024]; v1 = Whh[(size_t)orow * 1024 + col - 1023]; }
            __nv_bfloat162 bb = __floats2bfloat162_rn(v0, v1);
            o[reg] = *(unsigned*)&bb;
        }
        dW1p[u] = make_uint4(o[0], o[1], o[2], o[3]);
    }
}
__global__ void pk_wkp(const float* __restrict__ Wk) {
    const size_t N = (size_t)H_ * H_ / 8;
    for (size_t u = (size_t)blockIdx.x * blockDim.x + threadIdx.x; u < N;
         u += (size_t)gridDim.x * blockDim.x) {
        int lane = (int)(u & 31); size_t t1 = u >> 5; int mh = (int)(t1 & 1); size_t t2 = t1 >> 1;
        int p = (int)(t2 % 64); int jt = (int)(t2 / 64);
        int r = lane >> 2, ci = lane & 3;
        unsigned o[4];
#pragma unroll
        for (int reg = 0; reg < 4; reg++) {
            int rh = reg & 1, hi = reg >> 1;
            int row = jt * 32 + mh * 16 + rh * 8 + r;
            int col = p * 16 + hi * 8 + ci * 2;
            // WkT[row][col] = Wk[col][row]
            float v0 = Wk[(size_t)col * 1024 + row];
            float v1 = Wk[(size_t)(col + 1) * 1024 + row];
            __nv_bfloat162 bb = __floats2bfloat162_rn(v0, v1);
            o[reg] = *(unsigned*)&bb;
        }
        dWkp[u] = make_uint4(o[0], o[1], o[2], o[3]);
    }
}
__global__ void pk_wcp(const float* __restrict__ Wc) {
    const size_t N = (size_t)H_ * K1_ / 8;
    for (size_t u = (size_t)blockIdx.x * blockDim.x + threadIdx.x; u < N;
         u += (size_t)gridDim.x * blockDim.x) {
        int lane = (int)(u & 31); size_t t1 = u >> 5; int mh = (int)(t1 & 1); size_t t2 = t1 >> 1;
        int p = (int)(t2 % 128); int jt = (int)(t2 / 128);
        int r = lane >> 2, ci = lane & 3;
        unsigned o[4];
#pragma unroll
        for (int reg = 0; reg < 4; reg++) {
            int rh = reg & 1, hi = reg >> 1;
            int row = jt * 32 + mh * 16 + rh * 8 + r;
            int col = p * 16 + hi * 8 + ci * 2;
            float v0 = Wc[(size_t)row * 2048 + col];
            float v1 = Wc[(size_t)row * 2048 + col + 1];
            __nv_bfloat162 bb = __floats2bfloat162_rn(v0, v1);
            o[reg] = *(unsigned*)&bb;
        }
        dWcp[u] = make_uint4(o[0], o[1], o[2], o[3]);
    }
}
__global__ void pk_wp(const float* __restrict__ Wp) {
    for (size_t i = (size_t)blockIdx.x * blockDim.x + threadIdx.x; i < (size_t)V_ * H_;
         i += (size_t)gridDim.x * blockDim.x)
        dWp[i] = __float2bfloat16(Wp[i]);
}
__global__ void pk_state(const float* __restrict__ bih0, const float* __restrict__ bhh0,
                         const float* __restrict__ bih1, const float* __restrict__ bhh1,
                         const float* __restrict__ h0, const float* __restrict__ c0,
                         const float* __restrict__ Eb, const int* __restrict__ tok) {
    int i = blockIdx.x * blockDim.x + threadIdx.x;   // 32768 threads
    int bb = i >> 10, h = i & 1023;
    dC0[h * 32 + bb] = c0[(size_t)bb * H_ + h];
    dC1[h * 32 + bb] = c0[(size_t)B_ * H_ + (size_t)bb * H_ + h];
    ((__nv_bfloat16*)dX0p)[xpk(bb, 1536 + h)] = __float2bfloat16(h0[(size_t)bb * H_ + h]);
    ((__nv_bfloat16*)dX1p)[xpk(bb, 1024 + h)] =
        __float2bfloat16(h0[(size_t)B_ * H_ + (size_t)bb * H_ + h]);
    ((__nv_bfloat16*)dX0p)[xpk(bb, 512 + h)] = __float2bfloat16(0.0f);
    if (i < 4096) {
        int h2 = i >> 2, g = i & 3;
        dB0[i] = bih0[g * 1024 + h2] + bhh0[g * 1024 + h2];
        dB1[i] = bih1[g * 1024 + h2] + bhh1[g * 1024 + h2];
    }
    if (i < 32 * 512) {
        int b2 = i >> 9, e2 = i & 511;
        ((__nv_bfloat16*)dX0p)[xpk(b2, e2)] = __float2bfloat16(Eb[(size_t)tok[b2] * 512 + e2]);
    }
    if (i < NBLK) gArr[i] = 0;
    if (i == 0) gRel = 0;
}

// ---------------- logits GEMM: 128x128 double-buffered bf16 (padded smem) ----------------
__global__ void __launch_bounds__(256) gemm_logits(const float* __restrict__ bp) {
    int v0 = blockIdx.x * 128, r0 = blockIdx.y * 128;
    __shared__ __nv_bfloat16 As[2][128][24];
    __shared__ __nv_bfloat16 Bs[2][128][24];
    int tid = threadIdx.x, wid = tid >> 5, lane = tid & 31;
    int mh = wid >> 2, nq = wid & 3;
    int r = lane >> 2, c2 = (lane & 3) * 2;
    int lrow = tid >> 1, lseg = (tid & 1) * 8;
    float acc[4][4][4];
#pragma unroll
    for (int a = 0; a < 4; a++)
#pragma unroll
        for (int bb = 0; bb < 4; bb++)
#pragma unroll
            for (int c = 0; c < 4; c++) acc[a][bb][c] = 0.f;

    *(uint4*)&As[0][lrow][lseg] = *(const uint4*)&dA[(size_t)(r0 + lrow) * H_ + lseg];
    *(uint4*)&Bs[0][lrow][lseg] = *(const uint4*)&dWp[(size_t)(v0 + lrow) * H_ + lseg];
    __syncthreads();
    for (int ks = 0; ks < 64; ks++) {
        uint4 na, nb;
        if (ks < 63) {
            na = *(const uint4*)&dA[(size_t)(r0 + lrow) * H_ + (ks + 1) * 16 + lseg];
            nb = *(const uint4*)&dWp[(size_t)(v0 + lrow) * H_ + (ks + 1) * 16 + lseg];
        }
        int cur = ks & 1;
#pragma unroll
        for (int mi = 0; mi < 4; mi++) {
            int row = mh * 64 + mi * 16;
            unsigned a0 = *(unsigned*)&As[cur][row + r][c2];
            unsigned a1 = *(unsigned*)&As[cur][row + r + 8][c2];
            unsigned a2 = *(unsigned*)&As[cur][row + r][c2 + 8];
            unsigned a3 = *(unsigned*)&As[cur][row + r + 8][c2 + 8];
#pragma unroll
            for (int ni = 0; ni < 4; ni++) {
                int n = nq * 32 + ni * 8 + r;
                unsigned b0 = *(unsigned*)&Bs[cur][n][c2];
                unsigned b1 = *(unsigned*)&Bs[cur][n][c2 + 8];
                mma16(acc[mi][ni], a0, a1, a2, a3, b0, b1);
            }
        }
        __syncthreads();
        if (ks < 63) {
            *(uint4*)&As[cur ^ 1][lrow][lseg] = na;
            *(uint4*)&Bs[cur ^ 1][lrow][lseg] = nb;
        }
        __syncthreads();
    }
#pragma unroll
    for (int mi = 0; mi < 4; mi++) {
        int row = r0 + mh * 64 + mi * 16 + r;
#pragma unroll
        for (int ni = 0; ni < 4; ni++) {
            int col = v0 + nq * 32 + ni * 8 + c2;
            float b0 = bp[col], b1 = bp[col + 1];
            dLog[(size_t)row * V_ + col] = acc[mi][ni][0] + b0;
            dLog[(size_t)row * V_ + col + 1] = acc[mi][ni][1] + b1;
            dLog[(size_t)(row + 8) * V_ + col] = acc[mi][ni][2] + b0;
            dLog[(size_t)(row + 8) * V_ + col + 1] = acc[mi][ni][3] + b1;
        }
    }
}

// ---------------- softmax + mixture log output ----------------
__global__ void softmax_out(float* __restrict__ out) {
    int rr = blockIdx.x, tid = threadIdx.x;
    const float* L = dLog + (size_t)rr * V_;
    __shared__ float red[256];
    float m = -1e30f;
    for (int v = tid; v < V_; v += 256) m = fmaxf(m, L[v]);
    red[tid] = m; __syncthreads();
    for (int st = 128; st; st >>= 1) { if (tid < st) red[tid] = fmaxf(red[tid], red[tid + st]); __syncthreads(); }
    m = red[0]; __syncthreads();
    float s = 0.f;
    for (int v = tid; v < V_; v += 256) s += __expf(L[v] - m);
    red[tid] = s; __syncthreads();
    for (int st = 128; st; st >>= 1) { if (tid < st) red[tid] += red[tid + st]; __syncthreads(); }
    s = red[0];
    float inv = 1.0f / s;
    float cw = __expf(L[3] - m) * inv;        // COPY_ID = 3
    if (tid == 0) { dMx[rr] = m; dIs[rr] = inv; dCw[rr] = cw; }
    float ce = cw * 1e-7f, oc = 1.0f - cw;
    float* O = out + (size_t)rr * V_;
    for (int v = tid; v < V_; v += 256)
        O[v] = __logf(ce + oc * __expf(L[v] - m) * inv);
}

__global__ void fixup(float* __restrict__ out, const int* __restrict__ tok) {
    int rr = blockIdx.x;
    int t = rr >> 5, b = rr & 31;
    int s = threadIdx.x;
    __shared__ int tk[T_];
    __shared__ float dd[T_];
    tk[s] = tok[s * 32 + b];
    dd[s] = dDist[(t * T_ + s) * 32 + b];
    __syncthreads();
    int mytok = tk[s];
    float tot = 0.f;
    for (int s2 = 0; s2 < T_; s2++) if (tk[s2] == mytok) tot += dd[s2];
    float m = dMx[rr], inv = dIs[rr], cw = dCw[rr];
    float p = __expf(dLog[(size_t)rr * V_ + mytok] - m) * inv;
    out[(size_t)rr * V_ + mytok] = __logf(cw * (1e-7f + tot) + (1.0f - cw) * p);
}

// ---------------- host ----------------
extern "C" void kernel_launch(void* const* d_in, const int* in_sizes, int n_in,
                              void* d_out, int out_size) {
    const int* tok = (const int*)d_in[0];
    const float* h0 = (const float*)d_in[1];
    const float* c0 = (const float*)d_in[2];
    const float* Eb = (const float*)d_in[3];
    const float* Wih0 = (const float*)d_in[4];
    const float* Whh0 = (const float*)d_in[5];
    const float* bih0 = (const float*)d_in[6];
    const float* bhh0 = (const float*)d_in[7];
    const float* Wih1 = (const float*)d_in[8];
    const float* Whh1 = (const float*)d_in[9];
    const float* bih1 = (const float*)d_in[10];
    const float* bhh1 = (const float*)d_in[11];
    const float* Wk = (const float*)d_in[12];
    const float* bk = (const float*)d_in[13];
    const float* Wc = (const float*)d_in[14];
    const float* bc = (const float*)d_in[15];
    const float* Wp = (const float*)d_in[16];
    const float* bp = (const float*)d_in[17];
    float* out = (float*)d_out;

    pk_w0p<<<2048, 256>>>(Wih0, Whh0);
    pk_w1p<<<2048, 256>>>(Wih1, Whh1);
    pk_wkp<<<512, 256>>>(Wk);
    pk_wcp<<<1024, 256>>>(Wc);
    pk_wp<<<4096, 256>>>(Wp);
    pk_state<<<128, 256>>>(bih0, bhh0, bih1, bhh1, h0, c0, Eb, tok);

    decode_loop<<<NBLK, 256>>>(tok, Eb, bk, bc);

    gemm_logits<<<dim3(V_ / 128, (T_ * B_) / 128), 256>>>(bp);
    softmax_out<<<T_ * B_, 256>>>(out);
    fixup<<<T_ * B_, 64>>>(out, tok);
}

// round 8
// speedup vs baseline: 6.3440x; 1.1103x over previous
#include <cuda_runtime.h>
#include <cuda_bf16.h>
#include <stdint.h>
#include <math.h>

#define T_ 64
#define B_ 32
#define V_ 32000
#define H_ 1024
#define K0_ 2560
#define K1_ 2048
#define NBLK 128

// ---------------- device scratch ----------------
// fragment-packed weights: [jtile][panel(K/16)][mh(2)][lane(32)] uint4
__device__ uint4 dW0p[(size_t)4096 * K0_ / 8];
__device__ uint4 dW1p[(size_t)4096 * K1_ / 8];
__device__ uint4 dWkp[(size_t)H_ * H_ / 8];    // Wk^T packed (K=1024)
__device__ uint4 dWc1p[(size_t)H_ * H_ / 8];   // Wc[:, :1024] packed
__device__ uint4 dWc2p[(size_t)H_ * H_ / 8];   // Wc[:, 1024:] packed
__device__ __nv_bfloat16 dWp[(size_t)V_ * H_];
__device__ float dB0[4096], dB1[4096];
// fragment-packed activations, parity double-buffered
__device__ uint4 dX0p[2][(K0_ / 16) * 64];
__device__ uint4 dX1p[2][(K1_ / 16) * 64];
__device__ uint4 dXcp[(H_ / 16) * 64];         // htop only (K=1024)
__device__ float dC0[B_ * H_], dC1[B_ * H_];
__device__ float dQ[H_ * B_];
__device__ float dCb1[H_ * B_];                // Wc1 @ htop
__device__ float dM[(size_t)T_ * B_ * H_];     // Wc2 @ hbuf[s], [s][b][j]
__device__ __nv_bfloat16 dHBh[(size_t)T_ * B_ * H_];
__device__ float dDist[T_ * T_ * B_];
__device__ __nv_bfloat16 dA[(size_t)T_ * B_ * H_];
__device__ float dMx[T_ * B_], dIs[T_ * B_], dCw[T_ * B_];
__device__ float dLog[(size_t)T_ * B_ * V_];
__device__ int gArr[NBLK];
__device__ int gRel;

// ---------------- fast transcendentals (FMA pipe, not MUFU) ----------------
__device__ __forceinline__ float fexp(float x) {
    float t = fminf(fmaxf(x * 1.44269504f, -126.0f), 126.0f);
    float r = rintf(t);
    float f = t - r;
    float p = 1.3333558146e-3f;
    p = fmaf(p, f, 9.6181291076e-3f);
    p = fmaf(p, f, 5.5504108664e-2f);
    p = fmaf(p, f, 2.4022650696e-1f);
    p = fmaf(p, f, 6.9314718056e-1f);
    p = fmaf(p, f, 1.0f);
    return p * __int_as_float(((int)r + 127) << 23);
}
__device__ __forceinline__ float flog(float x) {
    int ix = __float_as_int(x);
    int e = (ix >> 23) - 127;
    float m = __int_as_float((ix & 0x7FFFFF) | 0x3F800000);
    if (m > 1.41421356f) { m *= 0.5f; e++; }
    float f = m - 1.0f;
    float z = f * f;
    float p = 7.0376836292e-2f;
    p = fmaf(p, f, -1.1514610310e-1f);
    p = fmaf(p, f, 1.1676998740e-1f);
    p = fmaf(p, f, -1.2420140846e-1f);
    p = fmaf(p, f, 1.4249322787e-1f);
    p = fmaf(p, f, -1.6668057665e-1f);
    p = fmaf(p, f, 2.0000714765e-1f);
    p = fmaf(p, f, -2.4999993993e-1f);
    p = fmaf(p, f, 3.3333331174e-1f);
    float y = fmaf(p * f, z, -0.5f * z) + f;
    return fmaf((float)e, 0.69314718056f, y);
}
__device__ __forceinline__ float fsig(float x) {
    return __fdividef(1.0f, 1.0f + fexp(-x));
}
__device__ __forceinline__ float ftanh(float x) {
    float e = fexp(-2.0f * fabsf(x));
    float t = __fdividef(1.0f - e, 1.0f + e);
    return x >= 0.f ? t : -t;
}

// packed-X bf16 index for activation value (n=batch, k=feature)
__device__ __forceinline__ int xpk(int n, int k) {
    int p = k >> 4, hi = (k >> 3) & 1, lo = k & 1, ci = (k >> 1) & 3;
    int nh = n >> 4, rh = (n >> 3) & 1, r = n & 7;
    return ((((p * 2 + nh) * 32 + (r * 4 + ci)) * 4) + (rh * 2 + hi)) * 2 + lo;
}

__device__ __forceinline__ float ldcgf(const float* p) {
    float v; asm volatile("ld.global.cg.f32 %0,[%1];" : "=f"(v) : "l"(p)); return v;
}
__device__ __forceinline__ uint4 ldcg4(const void* p) {
    uint4 v;
    asm volatile("ld.global.cg.v4.b32 {%0,%1,%2,%3},[%4];"
                 : "=r"(v.x), "=r"(v.y), "=r"(v.z), "=r"(v.w) : "l"(p));
    return v;
}
__device__ __forceinline__ void st_rel(int* p, int v) {
    asm volatile("st.release.gpu.global.s32 [%0],%1;" :: "l"(p), "r"(v) : "memory");
}
__device__ __forceinline__ int ld_acq(const int* p) {
    int v; asm volatile("ld.acquire.gpu.global.s32 %0,[%1];" : "=r"(v) : "l"(p) : "memory");
    return v;
}
__device__ __forceinline__ void mma16(float c[4], unsigned a0, unsigned a1,
                                      unsigned a2, unsigned a3, unsigned b0, unsigned b1) {
    asm volatile("mma.sync.aligned.m16n8k16.row.col.f32.bf16.bf16.f32 "
                 "{%0,%1,%2,%3},{%4,%5,%6,%7},{%8,%9},{%0,%1,%2,%3};"
                 : "+f"(c[0]), "+f"(c[1]), "+f"(c[2]), "+f"(c[3])
                 : "r"(a0), "r"(a1), "r"(a2), "r"(a3), "r"(b0), "r"(b1));
}

// ---------------- grid barrier ----------------
__device__ __forceinline__ void gbar(int e) {
    __syncthreads();
    if (threadIdx.x == 0) st_rel(&gArr[blockIdx.x], e);
    if (blockIdx.x == 0) {
        if (threadIdx.x < NBLK) while (ld_acq(&gArr[threadIdx.x]) < e) { }
        __syncthreads();
        if (threadIdx.x == 0) st_rel(&gRel, e);
    } else if (threadIdx.x == 0) {
        while (ld_acq(&gRel) < e) { }
    }
    __syncthreads();
}

// ---------------- packed 32x32xKC GEMM: 8 k-segment warps ----------------
template <int KC>
__device__ __forceinline__ void gemm_p(const uint4* __restrict__ Wt,
                                       const uint4* __restrict__ Xp,
                                       float (*G)[32][33]) {
    int tid = threadIdx.x, wid = tid >> 5, lane = tid & 31;
    constexpr int PPW = KC / 128;
    const uint4* Wr = Wt + (size_t)(wid * PPW * 2) * 32 + lane;
    const uint4* Xr = Xp + (size_t)(wid * PPW * 2) * 32 + lane;
    float c[2][4][4];
#pragma unroll
    for (int i = 0; i < 2; i++)
#pragma unroll
        for (int j = 0; j < 4; j++)
#pragma unroll
            for (int k = 0; k < 4; k++) c[i][j][k] = 0.f;
#pragma unroll 4
    for (int p = 0; p < PPW; p++) {
        uint4 A0 = Wr[p * 64];
        uint4 A1 = Wr[p * 64 + 32];
        uint4 B0 = ldcg4(Xr + p * 64);
        uint4 B1 = ldcg4(Xr + p * 64 + 32);
        mma16(c[0][0], A0.x, A0.y, A0.z, A0.w, B0.x, B0.y);
        mma16(c[0][1], A0.x, A0.y, A0.z, A0.w, B0.z, B0.w);
        mma16(c[0][2], A0.x, A0.y, A0.z, A0.w, B1.x, B1.y);
        mma16(c[0][3], A0.x, A0.y, A0.z, A0.w, B1.z, B1.w);
        mma16(c[1][0], A1.x, A1.y, A1.z, A1.w, B0.x, B0.y);
        mma16(c[1][1], A1.x, A1.y, A1.z, A1.w, B0.z, B0.w);
        mma16(c[1][2], A1.x, A1.y, A1.z, A1.w, B1.x, B1.y);
        mma16(c[1][3], A1.x, A1.y, A1.z, A1.w, B1.z, B1.w);
    }
    int r = lane >> 2, c2 = (lane & 3) * 2;
#pragma unroll
    for (int mh = 0; mh < 2; mh++)
#pragma unroll
        for (int q = 0; q < 4; q++) {
            int row = mh * 16 + r, col = (q >> 1) * 16 + (q & 1) * 8 + c2;
            G[wid][row][col] = c[mh][q][0];
            G[wid][row][col + 1] = c[mh][q][1];
            G[wid][row + 8][col] = c[mh][q][2];
            G[wid][row + 8][col + 1] = c[mh][q][3];
        }
}
__device__ __forceinline__ float gsum(float (*G)[32][33], int row, int b) {
    float s = 0.f;
#pragma unroll
    for (int k = 0; k < 8; k++) s += G[k][row][b];
    return s;
}

// ---------------- persistent decode loop: 4 phases/step ----------------
__global__ void __launch_bounds__(256, 1)
decode_loop(const int* __restrict__ tok, const float* __restrict__ Eb,
            const float* __restrict__ bk, const float* __restrict__ bc) {
    __shared__ __align__(16) float Gs[8][32][33];
    int bid = blockIdx.x, tid = threadIdx.x;
    int b = tid & 31, hl = tid >> 5;
    int e = 0;
    const uint4* W0t = dW0p + (size_t)bid * (160 * 64);
    const uint4* W1t = dW1p + (size_t)bid * (128 * 64);

    for (int t = 0; t < T_; t++) {
        int cur = t & 1, nxt = cur ^ 1;

        // ---- Phase A: layer-0 GEMM + LSTM pointwise ----
        gemm_p<K0_>(W0t, dX0p[cur], Gs);
        __syncthreads();
        {
            int h = bid * 8 + hl, j0 = bid * 32 + hl * 4;
            float g0 = gsum(Gs, hl * 4 + 0, b) + dB0[j0 + 0];
            float g1 = gsum(Gs, hl * 4 + 1, b) + dB0[j0 + 1];
            float g2 = gsum(Gs, hl * 4 + 2, b) + dB0[j0 + 2];
            float g3 = gsum(Gs, hl * 4 + 3, b) + dB0[j0 + 3];
            float c = dC0[h * 32 + b];
            float cn = fsig(g1) * c + fsig(g0) * ftanh(g2);
            float hn = fsig(g3) * ftanh(cn);
            dC0[h * 32 + b] = cn;
            __nv_bfloat16 hb = __float2bfloat16(hn);
            ((__nv_bfloat16*)dX1p[cur])[xpk(b, h)] = hb;         // layer-1 input
            ((__nv_bfloat16*)dX0p[nxt])[xpk(b, 1536 + h)] = hb;  // next-step h0
        }
        gbar(++e);

        // ---- Phase B: layer-1 GEMM + LSTM pointwise ----
        gemm_p<K1_>(W1t, dX1p[cur], Gs);
        __syncthreads();
        {
            int h = bid * 8 + hl, j0 = bid * 32 + hl * 4;
            float g0 = gsum(Gs, hl * 4 + 0, b) + dB1[j0 + 0];
            float g1 = gsum(Gs, hl * 4 + 1, b) + dB1[j0 + 1];
            float g2 = gsum(Gs, hl * 4 + 2, b) + dB1[j0 + 2];
            float g3 = gsum(Gs, hl * 4 + 3, b) + dB1[j0 + 3];
            float c = dC1[h * 32 + b];
            float cn = fsig(g1) * c + fsig(g0) * ftanh(g2);
            float hn = fsig(g3) * ftanh(cn);
            dC1[h * 32 + b] = cn;
            __nv_bfloat16 hb = __float2bfloat16(hn);
            ((__nv_bfloat16*)dXcp)[xpk(b, h)] = hb;              // htop
            ((__nv_bfloat16*)dX1p[nxt])[xpk(b, 1024 + h)] = hb;  // next-step h1
            dHBh[((size_t)t * 32 + b) * H_ + h] = hb;            // hbuf
        }
        gbar(++e);

        // ---- Phase C: q/M/comb1 GEMMs + emb prefetch ----
        if (bid < 32) {               // q = Wk^T @ htop
            gemm_p<H_>(dWkp + (size_t)bid * 4096, dXcp, Gs);
            __syncthreads();
#pragma unroll
            for (int g = 0; g < 4; g++) {
                int row = hl * 4 + g;
                dQ[(bid * 32 + row) * 32 + b] = gsum(Gs, row, b);
            }
        } else if (bid < 64) {        // M[t] = Wc2 @ htop
            int jt = bid - 32;
            gemm_p<H_>(dWc2p + (size_t)jt * 4096, dXcp, Gs);
            __syncthreads();
#pragma unroll
            for (int g = 0; g < 4; g++) {
                int row = hl * 4 + g;
                dM[((size_t)t * 32 + b) * H_ + jt * 32 + row] = gsum(Gs, row, b);
            }
        } else if (bid < 96) {        // comb1 = Wc1 @ htop
            int jt = bid - 64;
            gemm_p<H_>(dWc1p + (size_t)jt * 4096, dXcp, Gs);
            __syncthreads();
#pragma unroll
            for (int g = 0; g < 4; g++) {
                int row = hl * 4 + g;
                dCb1[(jt * 32 + row) * 32 + b] = gsum(Gs, row, b);
            }
        } else if (t + 1 < T_) {      // emb prefetch
            int bb = bid - 96;
            int tk = tok[(t + 1) * 32 + bb];
            for (int e2 = tid; e2 < 512; e2 += 256)
                ((__nv_bfloat16*)dX0p[nxt])[xpk(bb, e2)] =
                    __float2bfloat16(Eb[(size_t)tk * 512 + e2]);
        }
        gbar(++e);

        // ---- Phase D: attention + comb finalize (32 blocks) ----
        if (bid < 32) {
            int bb = bid;
            float* qv = (float*)Gs;          // 1024
            float* sc = qv + 1024;           // 64
            float* red = sc + 64;            // 256
            int h4 = tid * 4;
            {
                qv[h4 + 0] = ldcgf(&dQ[(h4 + 0) * 32 + bb]);
                qv[h4 + 1] = ldcgf(&dQ[(h4 + 1) * 32 + bb]);
                qv[h4 + 2] = ldcgf(&dQ[(h4 + 2) * 32 + bb]);
                qv[h4 + 3] = ldcgf(&dQ[(h4 + 3) * 32 + bb]);
                const __nv_bfloat16* ht = &dHBh[((size_t)t * 32 + bb) * H_ + h4];
                float4 bv = *(const float4*)&bk[h4];
                red[tid] = __bfloat162float(ht[0]) * bv.x + __bfloat162float(ht[1]) * bv.y
                         + __bfloat162float(ht[2]) * bv.z + __bfloat162float(ht[3]) * bv.w;
            }
            __syncthreads();
            for (int st = 128; st; st >>= 1) { if (tid < st) red[tid] += red[tid + st]; __syncthreads(); }
            float bkh = red[0];
            __syncthreads();
            int w = tid >> 5, lane = tid & 31;
            for (int si = w; si <= t; si += 8) {
                const __nv_bfloat16* hr = &dHBh[((size_t)si * 32 + bb) * H_];
                float acc = 0.f;
                for (int h = lane * 8; h < H_; h += 256) {
                    uint4 hv = *(const uint4*)(hr + h);
                    float2 a0 = __bfloat1622float2(*(__nv_bfloat162*)&hv.x);
                    float2 a1 = __bfloat1622float2(*(__nv_bfloat162*)&hv.y);
                    float2 a2 = __bfloat1622float2(*(__nv_bfloat162*)&hv.z);
                    float2 a3 = __bfloat1622float2(*(__nv_bfloat162*)&hv.w);
                    acc += a0.x * qv[h] + a0.y * qv[h + 1] + a1.x * qv[h + 2] + a1.y * qv[h + 3]
                         + a2.x * qv[h + 4] + a2.y * qv[h + 5] + a3.x * qv[h + 6] + a3.y * qv[h + 7];
                }
#pragma unroll
                for (int o = 16; o; o >>= 1) acc += __shfl_xor_sync(0xffffffffu, acc, o);
                if (!lane) {
                    float v = acc + bkh;
                    if (tok[si * 32 + bb] == 0) v += -99999.0f;
                    sc[si] = v;
                }
            }
            __syncthreads();
            // parallel softmax over sc[0..t]
            float v = (tid < 64 && tid <= t) ? sc[tid] : -1e30f;
            red[tid] = v; __syncthreads();
            for (int st = 128; st; st >>= 1) { if (tid < st) red[tid] = fmaxf(red[tid], red[tid + st]); __syncthreads(); }
            float m = red[0]; __syncthreads();
            float ev = (tid < 64 && tid <= t) ? fexp(v - m) : 0.f;
            red[tid] = ev; __syncthreads();
            for (int st = 128; st; st >>= 1) { if (tid < st) red[tid] += red[tid + st]; __syncthreads(); }
            float inv = 1.0f / red[0];
            if (tid < 64) sc[tid] = (tid <= t) ? ev * inv : 0.f;
            __syncthreads();
            for (int s = tid; s < T_; s += 256)
                dDist[(t * T_ + s) * 32 + bb] = sc[s];
            // comb = comb1 + sum_s dist_s * M[s] + bc ; write feed + A
            {
                int j = tid * 4;
                float a0 = ldcgf(&dCb1[(j + 0) * 32 + bb]);
                float a1 = ldcgf(&dCb1[(j + 1) * 32 + bb]);
                float a2 = ldcgf(&dCb1[(j + 2) * 32 + bb]);
                float a3 = ldcgf(&dCb1[(j + 3) * 32 + bb]);
#pragma unroll 4
                for (int s = 0; s <= t; s++) {
                    float d = sc[s];
                    float4 mv = *(const float4*)&dM[((size_t)s * 32 + bb) * H_ + j];
                    a0 = fmaf(d, mv.x, a0); a1 = fmaf(d, mv.y, a1);
                    a2 = fmaf(d, mv.z, a2); a3 = fmaf(d, mv.w, a3);
                }
                float4 bcv = *(const float4*)&bc[j];
                a0 += bcv.x; a1 += bcv.y; a2 += bcv.z; a3 += bcv.w;
                __nv_bfloat162 p0 = __floats2bfloat162_rn(a0, a1);
                __nv_bfloat162 p1 = __floats2bfloat162_rn(a2, a3);
                ((unsigned*)dX0p[nxt])[xpk(bb, 512 + j) >> 1] = *(unsigned*)&p0;
                ((unsigned*)dX0p[nxt])[xpk(bb, 512 + j + 2) >> 1] = *(unsigned*)&p1;
                *(unsigned*)&dA[((size_t)t * 32 + bb) * H_ + j] = *(unsigned*)&p0;
                *(unsigned*)&dA[((size_t)t * 32 + bb) * H_ + j + 2] = *(unsigned*)&p1;
            }
        }
        gbar(++e);
    }
}

// ---------------- weight pack kernels ----------------
__global__ void pk_w0p(const float* __restrict__ Wih, const float* __restrict__ Whh) {
    const size_t N = (size_t)4096 * K0_ / 8;
    for (size_t u = (size_t)blockIdx.x * blockDim.x + threadIdx.x; u < N;
         u += (size_t)gridDim.x * blockDim.x) {
        int lane = (int)(u & 31); size_t t1 = u >> 5; int mh = (int)(t1 & 1); size_t t2 = t1 >> 1;
        int p = (int)(t2 % 160); int jt = (int)(t2 / 160);
        int r = lane >> 2, ci = lane & 3;
        unsigned o[4];
#pragma unroll
        for (int reg = 0; reg < 4; reg++) {
            int rh = reg & 1, hi = reg >> 1;
            int row = jt * 32 + mh * 16 + rh * 8 + r;
            int orow = (row & 3) * 1024 + (row >> 2);
            int col = p * 16 + hi * 8 + ci * 2;
            float v0, v1;
            if (col < 1536) { v0 = Wih[(size_t)orow * 1536 + col]; v1 = Wih[(size_t)orow * 1536 + col + 1]; }
            else { v0 = Whh[(size_t)orow * 1024 + col - 1536]; v1 = Whh[(size_t)orow * 1024 + col - 1535]; }
            __nv_bfloat162 bb = __floats2bfloat162_rn(v0, v1);
            o[reg] = *(unsigned*)&bb;
        }
        dW0p[u] = make_uint4(o[0], o[1], o[2], o[3]);
    }
}
__global__ void pk_w1p(const float* __restrict__ Wih, const float* __restrict__ Whh) {
    const size_t N = (size_t)4096 * K1_ / 8;
    for (size_t u = (size_t)blockIdx.x * blockDim.x + threadIdx.x; u < N;
         u += (size_t)gridDim.x * blockDim.x) {
        int lane = (int)(u & 31); size_t t1 = u >> 5; int mh = (int)(t1 & 1); size_t t2 = t1 >> 1;
        int p = (int)(t2 % 128); int jt = (int)(t2 / 128);
        int r = lane >> 2, ci = lane & 3;
        unsigned o[4];
#pragma unroll
        for (int reg = 0; reg < 4; reg++) {
            int rh = reg & 1, hi = reg >> 1;
            int row = jt * 32 + mh * 16 + rh * 8 + r;
            int orow = (row & 3) * 1024 + (row >> 2);
            int col = p * 16 + hi * 8 + ci * 2;
            float v0, v1;
            if (col < 1024) { v0 = Wih[(size_t)orow * 1024 + col]; v1 = Wih[(size_t)orow * 1024 + col + 1]; }
            else { v0 = Whh[(size_t)orow * 1024 + col - 1024]; v1 = Whh[(size_t)orow * 1024 + col - 1023]; }
            __nv_bfloat162 bb = __floats2bfloat162_rn(v0, v1);
            o[reg] = *(unsigned*)&bb;
        }
        dW1p[u] = make_uint4(o[0], o[1], o[2], o[3]);
    }
}
// pack Wk^T, Wc1, Wc2 (each 1024x1024) in one kernel
__global__ void pk_wkc(const float* __restrict__ Wk, const float* __restrict__ Wc) {
    const size_t NP = (size_t)H_ * H_ / 8;   // per matrix
    for (size_t u = (size_t)blockIdx.x * blockDim.x + threadIdx.x; u < 3 * NP;
         u += (size_t)gridDim.x * blockDim.x) {
        int which = (int)(u / NP);
        size_t rem = u % NP;
        int lane = (int)(rem & 31); size_t t1 = rem >> 5; int mh = (int)(t1 & 1); size_t t2 = t1 >> 1;
        int p = (int)(t2 % 64); int jt = (int)(t2 / 64);
        int r = lane >> 2, ci = lane & 3;
        unsigned o[4];
#pragma unroll
        for (int reg = 0; reg < 4; reg++) {
            int rh = reg & 1, hi = reg >> 1;
            int row = jt * 32 + mh * 16 + rh * 8 + r;
            int col = p * 16 + hi * 8 + ci * 2;
            float v0, v1;
            if (which == 0) { v0 = Wk[(size_t)col * 1024 + row]; v1 = Wk[(size_t)(col + 1) * 1024 + row]; }
            else if (which == 1) { v0 = Wc[(size_t)row * 2048 + col]; v1 = Wc[(size_t)row * 2048 + col + 1]; }
            else { v0 = Wc[(size_t)row * 2048 + 1024 + col]; v1 = Wc[(size_t)row * 2048 + 1025 + col]; }
            __nv_bfloat162 bb = __floats2bfloat162_rn(v0, v1);
            o[reg] = *(unsigned*)&bb;
        }
        if (which == 0) dWkp[rem] = make_uint4(o[0], o[1], o[2], o[3]);
        else if (which == 1) dWc1p[rem] = make_uint4(o[0], o[1], o[2], o[3]);
        else dWc2p[rem] = make_uint4(o[0], o[1], o[2], o[3]);
    }
}
__global__ void pk_wp(const float* __restrict__ Wp) {
    for (size_t i = (size_t)blockIdx.x * blockDim.x + threadIdx.x; i < (size_t)V_ * H_;
         i += (size_t)gridDim.x * blockDim.x)
        dWp[i] = __float2bfloat16(Wp[i]);
}
__global__ void pk_state(const float* __restrict__ bih0, const float* __restrict__ bhh0,
                         const float* __restrict__ bih1, const float* __restrict__ bhh1,
                         const float* __restrict__ h0, const float* __restrict__ c0,
                         const float* __restrict__ Eb, const int* __restrict__ tok) {
    int i = blockIdx.x * blockDim.x + threadIdx.x;   // 32768 threads
    int bb = i >> 10, h = i & 1023;
    dC0[h * 32 + bb] = c0[(size_t)bb * H_ + h];
    dC1[h * 32 + bb] = c0[(size_t)B_ * H_ + (size_t)bb * H_ + h];
    ((__nv_bfloat16*)dX0p[0])[xpk(bb, 1536 + h)] = __float2bfloat16(h0[(size_t)bb * H_ + h]);
    ((__nv_bfloat16*)dX1p[0])[xpk(bb, 1024 + h)] =
        __float2bfloat16(h0[(size_t)B_ * H_ + (size_t)bb * H_ + h]);
    ((__nv_bfloat16*)dX0p[0])[xpk(bb, 512 + h)] = __float2bfloat16(0.0f);
    if (i < 4096) {
        int h2 = i >> 2, g = i & 3;
        dB0[i] = bih0[g * 1024 + h2] + bhh0[g * 1024 + h2];
        dB1[i] = bih1[g * 1024 + h2] + bhh1[g * 1024 + h2];
    }
    if (i < 32 * 512) {
        int b2 = i >> 9, e2 = i & 511;
        ((__nv_bfloat16*)dX0p[0])[xpk(b2, e2)] = __float2bfloat16(Eb[(size_t)tok[b2] * 512 + e2]);
    }
    if (i < NBLK) gArr[i] = 0;
    if (i == 0) gRel = 0;
}

// ---------------- logits GEMM: 128x128 double-buffered, 1 sync/iter ----------------
__global__ void __launch_bounds__(256) gemm_logits(const float* __restrict__ bp) {
    int v0 = blockIdx.x * 128, r0 = blockIdx.y * 128;
    __shared__ __nv_bfloat16 As[2][128][24];
    __shared__ __nv_bfloat16 Bs[2][128][24];
    int tid = threadIdx.x, wid = tid >> 5, lane = tid & 31;
    int mh = wid >> 2, nq = wid & 3;
    int r = lane >> 2, c2 = (lane & 3) * 2;
    int lrow = tid >> 1, lseg = (tid & 1) * 8;
    float acc[4][4][4];
#pragma unroll
    for (int a = 0; a < 4; a++)
#pragma unroll
        for (int bb = 0; bb < 4; bb++)
#pragma unroll
            for (int c = 0; c < 4; c++) acc[a][bb][c] = 0.f;

    *(uint4*)&As[0][lrow][lseg] = *(const uint4*)&dA[(size_t)(r0 + lrow) * H_ + lseg];
    *(uint4*)&Bs[0][lrow][lseg] = *(const uint4*)&dWp[(size_t)(v0 + lrow) * H_ + lseg];
    for (int ks = 0; ks < 64; ks++) {
        __syncthreads();
        uint4 na, nb;
        if (ks < 63) {
            na = *(const uint4*)&dA[(size_t)(r0 + lrow) * H_ + (ks + 1) * 16 + lseg];
            nb = *(const uint4*)&dWp[(size_t)(v0 + lrow) * H_ + (ks + 1) * 16 + lseg];
        }
        int cur = ks & 1;
#pragma unroll
        for (int mi = 0; mi < 4; mi++) {
            int row = mh * 64 + mi * 16;
            unsigned a0 = *(unsigned*)&As[cur][row + r][c2];
            unsigned a1 = *(unsigned*)&As[cur][row + r + 8][c2];
            unsigned a2 = *(unsigned*)&As[cur][row + r][c2 + 8];
            unsigned a3 = *(unsigned*)&As[cur][row + r + 8][c2 + 8];
#pragma unroll
            for (int ni = 0; ni < 4; ni++) {
                int n = nq * 32 + ni * 8 + r;
                unsigned b0 = *(unsigned*)&Bs[cur][n][c2];
                unsigned b1 = *(unsigned*)&Bs[cur][n][c2 + 8];
                mma16(acc[mi][ni], a0, a1, a2, a3, b0, b1);
            }
        }
        if (ks < 63) {
            *(uint4*)&As[cur ^ 1][lrow][lseg] = na;
            *(uint4*)&Bs[cur ^ 1][lrow][lseg] = nb;
        }
    }
#pragma unroll
    for (int mi = 0; mi < 4; mi++) {
        int row = r0 + mh * 64 + mi * 16 + r;
#pragma unroll
        for (int ni = 0; ni < 4; ni++) {
            int col = v0 + nq * 32 + ni * 8 + c2;
            float b0 = bp[col], b1 = bp[col + 1];
            dLog[(size_t)row * V_ + col] = acc[mi][ni][0] + b0;
            dLog[(size_t)row * V_ + col + 1] = acc[mi][ni][1] + b1;
            dLog[(size_t)(row + 8) * V_ + col] = acc[mi][ni][2] + b0;
            dLog[(size_t)(row + 8) * V_ + col + 1] = acc[mi][ni][3] + b1;
        }
    }
}

// ---------------- softmax (online, poly exp/log) + mixture log output ----------------
__global__ void softmax_out(float* __restrict__ out) {
    int rr = blockIdx.x, tid = threadIdx.x;
    const float* L = dLog + (size_t)rr * V_;
    __shared__ float rm[256], rs[256];
    float m = -1e30f, s = 0.f;
    for (int v = tid; v < V_; v += 256) {
        float x = L[v];
        if (x > m) { s = fmaf(s, fexp(m - x), 1.0f); m = x; }
        else s += fexp(x - m);
    }
    rm[tid] = m; rs[tid] = s; __syncthreads();
    for (int st = 128; st; st >>= 1) {
        if (tid < st) {
            float m2 = rm[tid + st], s2 = rs[tid + st];
            float M = fmaxf(rm[tid], m2);
            rs[tid] = rs[tid] * fexp(rm[tid] - M) + s2 * fexp(m2 - M);
            rm[tid] = M;
        }
        __syncthreads();
    }
    m = rm[0];
    float inv = 1.0f / rs[0];
    float cw = fexp(L[3] - m) * inv;          // COPY_ID = 3
    if (tid == 0) { dMx[rr] = m; dIs[rr] = inv; dCw[rr] = cw; }
    float ce = cw * 1e-7f, oc = (1.0f - cw) * inv;
    float* O = out + (size_t)rr * V_;
    for (int v = tid; v < V_; v += 256)
        O[v] = flog(fmaf(oc, fexp(L[v] - m), ce));
}

__global__ void fixup(float* __restrict__ out, const int* __restrict__ tok) {
    int rr = blockIdx.x;
    int t = rr >> 5, b = rr & 31;
    int s = threadIdx.x;
    __shared__ int tk[T_];
    __shared__ float dd[T_];
    tk[s] = tok[s * 32 + b];
    dd[s] = dDist[(t * T_ + s) * 32 + b];
    __syncthreads();
    int mytok = tk[s];
    float tot = 0.f;
    for (int s2 = 0; s2 < T_; s2++) if (tk[s2] == mytok) tot += dd[s2];
    float m = dMx[rr], inv = dIs[rr], cw = dCw[rr];
    float p = fexp(dLog[(size_t)rr * V_ + mytok] - m) * inv;
    out[(size_t)rr * V_ + mytok] = flog(cw * (1e-7f + tot) + (1.0f - cw) * p);
}

// ---------------- host ----------------
extern "C" void kernel_launch(void* const* d_in, const int* in_sizes, int n_in,
                              void* d_out, int out_size) {
    const int* tok = (const int*)d_in[0];
    const float* h0 = (const float*)d_in[1];
    const float* c0 = (const float*)d_in[2];
    const float* Eb = (const float*)d_in[3];
    const float* Wih0 = (const float*)d_in[4];
    const float* Whh0 = (const float*)d_in[5];
    const float* bih0 = (const float*)d_in[6];
    const float* bhh0 = (const float*)d_in[7];
    const float* Wih1 = (const float*)d_in[8];
    const float* Whh1 = (const float*)d_in[9];
    const float* bih1 = (const float*)d_in[10];
    const float* bhh1 = (const float*)d_in[11];
    const float* Wk = (const float*)d_in[12];
    const float* bk = (const float*)d_in[13];
    const float* Wc = (const float*)d_in[14];
    const float* bc = (const float*)d_in[15];
    const float* Wp = (const float*)d_in[16];
    const float* bp = (const float*)d_in[17];
    float* out = (float*)d_out;

    pk_w0p<<<2048, 256>>>(Wih0, Whh0);                       // launch 0
    pk_w1p<<<2048, 256>>>(Wih1, Whh1);                       // launch 1
    pk_wkc<<<1024, 256>>>(Wk, Wc);                           // launch 2
    pk_wp<<<4096, 256>>>(Wp);                                // launch 3
    pk_state<<<128, 256>>>(bih0, bhh0, bih1, bhh1, h0, c0, Eb, tok);  // launch 4

    decode_loop<<<NBLK, 256>>>(tok, Eb, bk, bc);             // launch 5 (ncu -s 5)

    gemm_logits<<<dim3(V_ / 128, (T_ * B_) / 128), 256>>>(bp);
    softmax_out<<<T_ * B_, 256>>>(out);
    fixup<<<T_ * B_, 64>>>(out, tok);
}

// round 9
// speedup vs baseline: 6.7721x; 1.0675x over previous
#include <cuda_runtime.h>
#include <cuda_bf16.h>
#include <stdint.h>
#include <math.h>

#define T_ 64
#define B_ 32
#define V_ 32000
#define H_ 1024
#define K0_ 2560
#define K1_ 2048
#define NBLK 128

// ---------------- device scratch ----------------
__device__ uint4 dW0p[(size_t)4096 * K0_ / 8];
__device__ uint4 dW1p[(size_t)4096 * K1_ / 8];
__device__ uint4 dWkp[(size_t)H_ * H_ / 8];
__device__ uint4 dWc1p[(size_t)H_ * H_ / 8];
__device__ uint4 dWc2p[(size_t)H_ * H_ / 8];
__device__ __nv_bfloat16 dWp[(size_t)V_ * H_];
__device__ float dB0[4096], dB1[4096];
__device__ uint4 dX0p[2][(K0_ / 16) * 64];
__device__ uint4 dX1p[2][(K1_ / 16) * 64];
__device__ uint4 dXcp[(H_ / 16) * 64];
__device__ float dC0[B_ * H_], dC1[B_ * H_];
__device__ float dQ[H_ * B_];
__device__ float dCb1[H_ * B_];
__device__ float dM[(size_t)T_ * B_ * H_];
__device__ __nv_bfloat16 dHBh[(size_t)T_ * B_ * H_];
__device__ float dDist[T_ * T_ * B_];
__device__ __nv_bfloat16 dA[(size_t)T_ * B_ * H_];
__device__ float dMx[T_ * B_], dIs[T_ * B_], dCw[T_ * B_];
__device__ float dLog[(size_t)T_ * B_ * V_];
__device__ int gCnt;
__device__ int gRel;

// ---------------- fast transcendentals (FMA pipe) ----------------
__device__ __forceinline__ float fexp(float x) {
    float t = fminf(fmaxf(x * 1.44269504f, -126.0f), 126.0f);
    float r = rintf(t);
    float f = t - r;
    float p = 1.3333558146e-3f;
    p = fmaf(p, f, 9.6181291076e-3f);
    p = fmaf(p, f, 5.5504108664e-2f);
    p = fmaf(p, f, 2.4022650696e-1f);
    p = fmaf(p, f, 6.9314718056e-1f);
    p = fmaf(p, f, 1.0f);
    return p * __int_as_float(((int)r + 127) << 23);
}
__device__ __forceinline__ float flog(float x) {
    int ix = __float_as_int(x);
    int e = (ix >> 23) - 127;
    float m = __int_as_float((ix & 0x7FFFFF) | 0x3F800000);
    if (m > 1.41421356f) { m *= 0.5f; e++; }
    float f = m - 1.0f;
    float z = f * f;
    float p = 7.0376836292e-2f;
    p = fmaf(p, f, -1.1514610310e-1f);
    p = fmaf(p, f, 1.1676998740e-1f);
    p = fmaf(p, f, -1.2420140846e-1f);
    p = fmaf(p, f, 1.4249322787e-1f);
    p = fmaf(p, f, -1.6668057665e-1f);
    p = fmaf(p, f, 2.0000714765e-1f);
    p = fmaf(p, f, -2.4999993993e-1f);
    p = fmaf(p, f, 3.3333331174e-1f);
    float y = fmaf(p * f, z, -0.5f * z) + f;
    return fmaf((float)e, 0.69314718056f, y);
}
__device__ __forceinline__ float fsig(float x) {
    return __fdividef(1.0f, 1.0f + fexp(-x));
}
__device__ __forceinline__ float ftanh(float x) {
    float e = fexp(-2.0f * fabsf(x));
    float t = __fdividef(1.0f - e, 1.0f + e);
    return x >= 0.f ? t : -t;
}

__device__ __forceinline__ int xpk(int n, int k) {
    int p = k >> 4, hi = (k >> 3) & 1, lo = k & 1, ci = (k >> 1) & 3;
    int nh = n >> 4, rh = (n >> 3) & 1, r = n & 7;
    return ((((p * 2 + nh) * 32 + (r * 4 + ci)) * 4) + (rh * 2 + hi)) * 2 + lo;
}

__device__ __forceinline__ float ldcgf(const float* p) {
    float v; asm volatile("ld.global.cg.f32 %0,[%1];" : "=f"(v) : "l"(p)); return v;
}
__device__ __forceinline__ uint4 ldcg4(const void* p) {
    uint4 v;
    asm volatile("ld.global.cg.v4.b32 {%0,%1,%2,%3},[%4];"
                 : "=r"(v.x), "=r"(v.y), "=r"(v.z), "=r"(v.w) : "l"(p));
    return v;
}
__device__ __forceinline__ void st_rel(int* p, int v) {
    asm volatile("st.release.gpu.global.s32 [%0],%1;" :: "l"(p), "r"(v) : "memory");
}
__device__ __forceinline__ int ld_acq(const int* p) {
    int v; asm volatile("ld.acquire.gpu.global.s32 %0,[%1];" : "=r"(v) : "l"(p) : "memory");
    return v;
}
__device__ __forceinline__ int atom_add_rel(int* p, int v) {
    int old;
    asm volatile("atom.release.gpu.global.add.s32 %0,[%1],%2;"
                 : "=r"(old) : "l"(p), "r"(v) : "memory");
    return old;
}
__device__ __forceinline__ void mma16(float c[4], unsigned a0, unsigned a1,
                                      unsigned a2, unsigned a3, unsigned b0, unsigned b1) {
    asm volatile("mma.sync.aligned.m16n8k16.row.col.f32.bf16.bf16.f32 "
                 "{%0,%1,%2,%3},{%4,%5,%6,%7},{%8,%9},{%0,%1,%2,%3};"
                 : "+f"(c[0]), "+f"(c[1]), "+f"(c[2]), "+f"(c[3])
                 : "r"(a0), "r"(a1), "r"(a2), "r"(a3), "r"(b0), "r"(b1));
}

// ---------------- grid barrier: single atomic arrival counter ----------------
__device__ __forceinline__ void gbar(int e) {
    __syncthreads();
    if (threadIdx.x == 0) {
        int v = atom_add_rel(&gCnt, 1);
        if (v == e * NBLK - 1) st_rel(&gRel, e);
        else while (ld_acq(&gRel) < e) { }
    }
    __syncthreads();
}

// ---------------- pipelined packed 32x32xKC GEMM: 8 k-segment warps ----------------
template <int KC>
__device__ __forceinline__ void gemm_p(const uint4* __restrict__ Wt,
                                       const uint4* __restrict__ Xp,
                                       float (*G)[32][33]) {
    int tid = threadIdx.x, wid = tid >> 5, lane = tid & 31;
    constexpr int PPW = KC / 128;   // panels per warp (20 / 16 / 8)
    constexpr int GRP = 4;          // panels per prefetch group
    const uint4* Wr = Wt + (size_t)(wid * PPW * 2) * 32 + lane;
    const uint4* Xr = Xp + (size_t)(wid * PPW * 2) * 32 + lane;
    float c[2][4][4];
#pragma unroll
    for (int i = 0; i < 2; i++)
#pragma unroll
        for (int j = 0; j < 4; j++)
#pragma unroll
            for (int k = 0; k < 4; k++) c[i][j][k] = 0.f;
#pragma unroll
    for (int pg = 0; pg < PPW / GRP; pg++) {
        uint4 Bv[GRP][2];
#pragma unroll
        for (int q = 0; q < GRP; q++) {          // 8 loads issued back-to-back (MLP=8)
            Bv[q][0] = ldcg4(Xr + (pg * GRP + q) * 64);
            Bv[q][1] = ldcg4(Xr + (pg * GRP + q) * 64 + 32);
        }
#pragma unroll
        for (int q = 0; q < GRP; q++) {
            uint4 A0 = Wr[(pg * GRP + q) * 64];
            uint4 A1 = Wr[(pg * GRP + q) * 64 + 32];
            mma16(c[0][0], A0.x, A0.y, A0.z, A0.w, Bv[q][0].x, Bv[q][0].y);
            mma16(c[0][1], A0.x, A0.y, A0.z, A0.w, Bv[q][0].z, Bv[q][0].w);
            mma16(c[0][2], A0.x, A0.y, A0.z, A0.w, Bv[q][1].x, Bv[q][1].y);
            mma16(c[0][3], A0.x, A0.y, A0.z, A0.w, Bv[q][1].z, Bv[q][1].w);
            mma16(c[1][0], A1.x, A1.y, A1.z, A1.w, Bv[q][0].x, Bv[q][0].y);
            mma16(c[1][1], A1.x, A1.y, A1.z, A1.w, Bv[q][0].z, Bv[q][0].w);
            mma16(c[1][2], A1.x, A1.y, A1.z, A1.w, Bv[q][1].x, Bv[q][1].y);
            mma16(c[1][3], A1.x, A1.y, A1.z, A1.w, Bv[q][1].z, Bv[q][1].w);
        }
    }
    int r = lane >> 2, c2 = (lane & 3) * 2;
#pragma unroll
    for (int mh = 0; mh < 2; mh++)
#pragma unroll
        for (int q = 0; q < 4; q++) {
            int row = mh * 16 + r, col = (q >> 1) * 16 + (q & 1) * 8 + c2;
            G[wid][row][col] = c[mh][q][0];
            G[wid][row][col + 1] = c[mh][q][1];
            G[wid][row + 8][col] = c[mh][q][2];
            G[wid][row + 8][col + 1] = c[mh][q][3];
        }
}
__device__ __forceinline__ float gsum(float (*G)[32][33], int row, int b) {
    float s = 0.f;
#pragma unroll
    for (int k = 0; k < 8; k++) s += G[k][row][b];
    return s;
}

// ---------------- persistent decode loop: 4 phases/step ----------------
__global__ void __launch_bounds__(256, 1)
decode_loop(const int* __restrict__ tok, const float* __restrict__ Eb,
            const float* __restrict__ bk, const float* __restrict__ bc) {
    __shared__ __align__(16) float Gs[8][32][33];
    int bid = blockIdx.x, tid = threadIdx.x;
    int b = tid & 31, hl = tid >> 5;
    int e = 0;
    const uint4* W0t = dW0p + (size_t)bid * (160 * 64);
    const uint4* W1t = dW1p + (size_t)bid * (128 * 64);

    for (int t = 0; t < T_; t++) {
        int cur = t & 1, nxt = cur ^ 1;

        // ---- Phase A: layer-0 GEMM + LSTM pointwise ----
        gemm_p<K0_>(W0t, dX0p[cur], Gs);
        __syncthreads();
        {
            int h = bid * 8 + hl, j0 = bid * 32 + hl * 4;
            float g0 = gsum(Gs, hl * 4 + 0, b) + dB0[j0 + 0];
            float g1 = gsum(Gs, hl * 4 + 1, b) + dB0[j0 + 1];
            float g2 = gsum(Gs, hl * 4 + 2, b) + dB0[j0 + 2];
            float g3 = gsum(Gs, hl * 4 + 3, b) + dB0[j0 + 3];
            float c = dC0[h * 32 + b];
            float cn = fsig(g1) * c + fsig(g0) * ftanh(g2);
            float hn = fsig(g3) * ftanh(cn);
            dC0[h * 32 + b] = cn;
            __nv_bfloat16 hb = __float2bfloat16(hn);
            ((__nv_bfloat16*)dX1p[cur])[xpk(b, h)] = hb;
            ((__nv_bfloat16*)dX0p[nxt])[xpk(b, 1536 + h)] = hb;
        }
        gbar(++e);

        // ---- Phase B: layer-1 GEMM + LSTM pointwise ----
        gemm_p<K1_>(W1t, dX1p[cur], Gs);
        __syncthreads();
        {
            int h = bid * 8 + hl, j0 = bid * 32 + hl * 4;
            float g0 = gsum(Gs, hl * 4 + 0, b) + dB1[j0 + 0];
            float g1 = gsum(Gs, hl * 4 + 1, b) + dB1[j0 + 1];
            float g2 = gsum(Gs, hl * 4 + 2, b) + dB1[j0 + 2];
            float g3 = gsum(Gs, hl * 4 + 3, b) + dB1[j0 + 3];
            float c = dC1[h * 32 + b];
            float cn = fsig(g1) * c + fsig(g0) * ftanh(g2);
            float hn = fsig(g3) * ftanh(cn);
            dC1[h * 32 + b] = cn;
            __nv_bfloat16 hb = __float2bfloat16(hn);
            ((__nv_bfloat16*)dXcp)[xpk(b, h)] = hb;
            ((__nv_bfloat16*)dX1p[nxt])[xpk(b, 1024 + h)] = hb;
            dHBh[((size_t)t * 32 + b) * H_ + h] = hb;
        }
        gbar(++e);

        // ---- Phase C: q/M/comb1 GEMMs + emb prefetch ----
        if (bid < 32) {
            gemm_p<H_>(dWkp + (size_t)bid * 4096, dXcp, Gs);
            __syncthreads();
#pragma unroll
            for (int g = 0; g < 4; g++) {
                int row = hl * 4 + g;
                dQ[(bid * 32 + row) * 32 + b] = gsum(Gs, row, b);
            }
        } else if (bid < 64) {
            int jt = bid - 32;
            gemm_p<H_>(dWc2p + (size_t)jt * 4096, dXcp, Gs);
            __syncthreads();
#pragma unroll
            for (int g = 0; g < 4; g++) {
                int row = hl * 4 + g;
                dM[((size_t)t * 32 + b) * H_ + jt * 32 + row] = gsum(Gs, row, b);
            }
        } else if (bid < 96) {
            int jt = bid - 64;
            gemm_p<H_>(dWc1p + (size_t)jt * 4096, dXcp, Gs);
            __syncthreads();
#pragma unroll
            for (int g = 0; g < 4; g++) {
                int row = hl * 4 + g;
                dCb1[(jt * 32 + row) * 32 + b] = gsum(Gs, row, b);
            }
        } else if (t + 1 < T_) {
            int bb = bid - 96;
            int tk = tok[(t + 1) * 32 + bb];
            for (int e2 = tid; e2 < 512; e2 += 256)
                ((__nv_bfloat16*)dX0p[nxt])[xpk(bb, e2)] =
                    __float2bfloat16(Eb[(size_t)tk * 512 + e2]);
        }
        gbar(++e);

        // ---- Phase D: attention + comb finalize (32 blocks) ----
        if (bid < 32) {
            int bb = bid;
            float* qv = (float*)Gs;          // 1024
            float* sc = qv + 1024;           // 64
            float* red = sc + 64;            // 256
            int h4 = tid * 4;
            {
                qv[h4 + 0] = ldcgf(&dQ[(h4 + 0) * 32 + bb]);
                qv[h4 + 1] = ldcgf(&dQ[(h4 + 1) * 32 + bb]);
                qv[h4 + 2] = ldcgf(&dQ[(h4 + 2) * 32 + bb]);
                qv[h4 + 3] = ldcgf(&dQ[(h4 + 3) * 32 + bb]);
                const __nv_bfloat16* ht = &dHBh[((size_t)t * 32 + bb) * H_ + h4];
                float4 bv = *(const float4*)&bk[h4];
                red[tid] = __bfloat162float(ht[0]) * bv.x + __bfloat162float(ht[1]) * bv.y
                         + __bfloat162float(ht[2]) * bv.z + __bfloat162float(ht[3]) * bv.w;
            }
            __syncthreads();
            for (int st = 128; st; st >>= 1) { if (tid < st) red[tid] += red[tid + st]; __syncthreads(); }
            float bkh = red[0];
            __syncthreads();
            int w = tid >> 5, lane = tid & 31;
            for (int si = w; si <= t; si += 8) {
                const __nv_bfloat16* hr = &dHBh[((size_t)si * 32 + bb) * H_];
                float acc = 0.f;
                for (int h = lane * 8; h < H_; h += 256) {
                    uint4 hv = *(const uint4*)(hr + h);
                    float2 a0 = __bfloat1622float2(*(__nv_bfloat162*)&hv.x);
                    float2 a1 = __bfloat1622float2(*(__nv_bfloat162*)&hv.y);
                    float2 a2 = __bfloat1622float2(*(__nv_bfloat162*)&hv.z);
                    float2 a3 = __bfloat1622float2(*(__nv_bfloat162*)&hv.w);
                    acc += a0.x * qv[h] + a0.y * qv[h + 1] + a1.x * qv[h + 2] + a1.y * qv[h + 3]
                         + a2.x * qv[h + 4] + a2.y * qv[h + 5] + a3.x * qv[h + 6] + a3.y * qv[h + 7];
                }
#pragma unroll
                for (int o = 16; o; o >>= 1) acc += __shfl_xor_sync(0xffffffffu, acc, o);
                if (!lane) {
                    float v = acc + bkh;
                    if (tok[si * 32 + bb] == 0) v += -99999.0f;
                    sc[si] = v;
                }
            }
            __syncthreads();
            float v = (tid < 64 && tid <= t) ? sc[tid] : -1e30f;
            red[tid] = v; __syncthreads();
            for (int st = 128; st; st >>= 1) { if (tid < st) red[tid] = fmaxf(red[tid], red[tid + st]); __syncthreads(); }
            float m = red[0]; __syncthreads();
            float ev = (tid < 64 && tid <= t) ? fexp(v - m) : 0.f;
            red[tid] = ev; __syncthreads();
            for (int st = 128; st; st >>= 1) { if (tid < st) red[tid] += red[tid + st]; __syncthreads(); }
            float inv = 1.0f / red[0];
            if (tid < 64) sc[tid] = (tid <= t) ? ev * inv : 0.f;
            __syncthreads();
            for (int s = tid; s < T_; s += 256)
                dDist[(t * T_ + s) * 32 + bb] = sc[s];
            {
                int j = tid * 4;
                float a0 = ldcgf(&dCb1[(j + 0) * 32 + bb]);
                float a1 = ldcgf(&dCb1[(j + 1) * 32 + bb]);
                float a2 = ldcgf(&dCb1[(j + 2) * 32 + bb]);
                float a3 = ldcgf(&dCb1[(j + 3) * 32 + bb]);
#pragma unroll 4
                for (int s = 0; s <= t; s++) {
                    float d = sc[s];
                    float4 mv = *(const float4*)&dM[((size_t)s * 32 + bb) * H_ + j];
                    a0 = fmaf(d, mv.x, a0); a1 = fmaf(d, mv.y, a1);
                    a2 = fmaf(d, mv.z, a2); a3 = fmaf(d, mv.w, a3);
                }
                float4 bcv = *(const float4*)&bc[j];
                a0 += bcv.x; a1 += bcv.y; a2 += bcv.z; a3 += bcv.w;
                __nv_bfloat162 p0 = __floats2bfloat162_rn(a0, a1);
                __nv_bfloat162 p1 = __floats2bfloat162_rn(a2, a3);
                ((unsigned*)dX0p[nxt])[xpk(bb, 512 + j) >> 1] = *(unsigned*)&p0;
                ((unsigned*)dX0p[nxt])[xpk(bb, 512 + j + 2) >> 1] = *(unsigned*)&p1;
                *(unsigned*)&dA[((size_t)t * 32 + bb) * H_ + j] = *(unsigned*)&p0;
                *(unsigned*)&dA[((size_t)t * 32 + bb) * H_ + j + 2] = *(unsigned*)&p1;
            }
        }
        gbar(++e);
    }
}

// ---------------- prep kernel 0: pack W0 + W1 ----------------
__global__ void pk_big(const float* __restrict__ Wih0, const float* __restrict__ Whh0,
                       const float* __restrict__ Wih1, const float* __restrict__ Whh1) {
    const size_t N0 = (size_t)4096 * K0_ / 8;
    const size_t N1 = (size_t)4096 * K1_ / 8;
    for (size_t uu = (size_t)blockIdx.x * blockDim.x + threadIdx.x; uu < N0 + N1;
         uu += (size_t)gridDim.x * blockDim.x) {
        bool first = uu < N0;
        size_t u = first ? uu : uu - N0;
        int PAN = first ? 160 : 128;
        const float* Wih = first ? Wih0 : Wih1;
        const float* Whh = first ? Whh0 : Whh1;
        int KIH = first ? 1536 : 1024;
        int lane = (int)(u & 31); size_t t1 = u >> 5; int mh = (int)(t1 & 1); size_t t2 = t1 >> 1;
        int p = (int)(t2 % PAN); int jt = (int)(t2 / PAN);
        int r = lane >> 2, ci = lane & 3;
        unsigned o[4];
#pragma unroll
        for (int reg = 0; reg < 4; reg++) {
            int rh = reg & 1, hi = reg >> 1;
            int row = jt * 32 + mh * 16 + rh * 8 + r;
            int orow = (row & 3) * 1024 + (row >> 2);
            int col = p * 16 + hi * 8 + ci * 2;
            float v0, v1;
            if (col < KIH) { v0 = Wih[(size_t)orow * KIH + col]; v1 = Wih[(size_t)orow * KIH + col + 1]; }
            else { v0 = Whh[(size_t)orow * 1024 + col - KIH]; v1 = Whh[(size_t)orow * 1024 + col - KIH + 1]; }
            __nv_bfloat162 bb = __floats2bfloat162_rn(v0, v1);
            o[reg] = *(unsigned*)&bb;
        }
        if (first) dW0p[u] = make_uint4(o[0], o[1], o[2], o[3]);
        else dW1p[u] = make_uint4(o[0], o[1], o[2], o[3]);
    }
}

// ---------------- prep kernel 1: pack Wk^T/Wc1/Wc2 + cast Wp ----------------
__global__ void pk_small(const float* __restrict__ Wk, const float* __restrict__ Wc,
                         const float* __restrict__ Wp) {
    const size_t NP = (size_t)H_ * H_ / 8;      // per 1024x1024 matrix
    const size_t NW = (size_t)V_ * H_ / 8;      // Wp in 8-element chunks
    for (size_t uu = (size_t)blockIdx.x * blockDim.x + threadIdx.x; uu < 3 * NP + NW;
         uu += (size_t)gridDim.x * blockDim.x) {
        if (uu < 3 * NP) {
            int which = (int)(uu / NP);
            size_t rem = uu % NP;
            int lane = (int)(rem & 31); size_t t1 = rem >> 5; int mh = (int)(t1 & 1); size_t t2 = t1 >> 1;
            int p = (int)(t2 % 64); int jt = (int)(t2 / 64);
            int r = lane >> 2, ci = lane & 3;
            unsigned o[4];
#pragma unroll
            for (int reg = 0; reg < 4; reg++) {
                int rh = reg & 1, hi = reg >> 1;
                int row = jt * 32 + mh * 16 + rh * 8 + r;
                int col = p * 16 + hi * 8 + ci * 2;
                float v0, v1;
                if (which == 0) { v0 = Wk[(size_t)col * 1024 + row]; v1 = Wk[(size_t)(col + 1) * 1024 + row]; }
                else if (which == 1) { v0 = Wc[(size_t)row * 2048 + col]; v1 = Wc[(size_t)row * 2048 + col + 1]; }
                else { v0 = Wc[(size_t)row * 2048 + 1024 + col]; v1 = Wc[(size_t)row * 2048 + 1025 + col]; }
                __nv_bfloat162 bb = __floats2bfloat162_rn(v0, v1);
                o[reg] = *(unsigned*)&bb;
            }
            if (which == 0) dWkp[rem] = make_uint4(o[0], o[1], o[2], o[3]);
            else if (which == 1) dWc1p[rem] = make_uint4(o[0], o[1], o[2], o[3]);
            else dWc2p[rem] = make_uint4(o[0], o[1], o[2], o[3]);
        } else {
            size_t w = uu - 3 * NP;
            float4 f0 = *(const float4*)(Wp + w * 8);
            float4 f1 = *(const float4*)(Wp + w * 8 + 4);
            __nv_bfloat162 b0 = __floats2bfloat162_rn(f0.x, f0.y);
            __nv_bfloat162 b1 = __floats2bfloat162_rn(f0.z, f0.w);
            __nv_bfloat162 b2 = __floats2bfloat162_rn(f1.x, f1.y);
            __nv_bfloat162 b3 = __floats2bfloat162_rn(f1.z, f1.w);
            ((uint4*)dWp)[w] = make_uint4(*(unsigned*)&b0, *(unsigned*)&b1,
                                          *(unsigned*)&b2, *(unsigned*)&b3);
        }
    }
}

// ---------------- prep kernel 2: state init ----------------
__global__ void pk_state(const float* __restrict__ bih0, const float* __restrict__ bhh0,
                         const float* __restrict__ bih1, const float* __restrict__ bhh1,
                         const float* __restrict__ h0, const float* __restrict__ c0,
                         const float* __restrict__ Eb, const int* __restrict__ tok) {
    int i = blockIdx.x * blockDim.x + threadIdx.x;   // 32768 threads
    int bb = i >> 10, h = i & 1023;
    dC0[h * 32 + bb] = c0[(size_t)bb * H_ + h];
    dC1[h * 32 + bb] = c0[(size_t)B_ * H_ + (size_t)bb * H_ + h];
    ((__nv_bfloat16*)dX0p[0])[xpk(bb, 1536 + h)] = __float2bfloat16(h0[(size_t)bb * H_ + h]);
    ((__nv_bfloat16*)dX1p[0])[xpk(bb, 1024 + h)] =
        __float2bfloat16(h0[(size_t)B_ * H_ + (size_t)bb * H_ + h]);
    ((__nv_bfloat16*)dX0p[0])[xpk(bb, 512 + h)] = __float2bfloat16(0.0f);
    if (i < 4096) {
        int h2 = i >> 2, g = i & 3;
        dB0[i] = bih0[g * 1024 + h2] + bhh0[g * 1024 + h2];
        dB1[i] = bih1[g * 1024 + h2] + bhh1[g * 1024 + h2];
    }
    if (i < 32 * 512) {
        int b2 = i >> 9, e2 = i & 511;
        ((__nv_bfloat16*)dX0p[0])[xpk(b2, e2)] = __float2bfloat16(Eb[(size_t)tok[b2] * 512 + e2]);
    }
    if (i == 0) { gCnt = 0; gRel = 0; }
}

// ---------------- logits GEMM: 128x128 double-buffered ----------------
__global__ void __launch_bounds__(256) gemm_logits(const float* __restrict__ bp) {
    int v0 = blockIdx.x * 128, r0 = blockIdx.y * 128;
    __shared__ __nv_bfloat16 As[2][128][24];
    __shared__ __nv_bfloat16 Bs[2][128][24];
    int tid = threadIdx.x, wid = tid >> 5, lane = tid & 31;
    int mh = wid >> 2, nq = wid & 3;
    int r = lane >> 2, c2 = (lane & 3) * 2;
    int lrow = tid >> 1, lseg = (tid & 1) * 8;
    float acc[4][4][4];
#pragma unroll
    for (int a = 0; a < 4; a++)
#pragma unroll
        for (int bb = 0; bb < 4; bb++)
#pragma unroll
            for (int c = 0; c < 4; c++) acc[a][bb][c] = 0.f;

    *(uint4*)&As[0][lrow][lseg] = *(const uint4*)&dA[(size_t)(r0 + lrow) * H_ + lseg];
    *(uint4*)&Bs[0][lrow][lseg] = *(const uint4*)&dWp[(size_t)(v0 + lrow) * H_ + lseg];
    for (int ks = 0; ks < 64; ks++) {
        __syncthreads();
        uint4 na, nb;
        if (ks < 63) {
            na = *(const uint4*)&dA[(size_t)(r0 + lrow) * H_ + (ks + 1) * 16 + lseg];
            nb = *(const uint4*)&dWp[(size_t)(v0 + lrow) * H_ + (ks + 1) * 16 + lseg];
        }
        int cur = ks & 1;
#pragma unroll
        for (int mi = 0; mi < 4; mi++) {
            int row = mh * 64 + mi * 16;
            unsigned a0 = *(unsigned*)&As[cur][row + r][c2];
            unsigned a1 = *(unsigned*)&As[cur][row + r + 8][c2];
            unsigned a2 = *(unsigned*)&As[cur][row + r][c2 + 8];
            unsigned a3 = *(unsigned*)&As[cur][row + r + 8][c2 + 8];
#pragma unroll
            for (int ni = 0; ni < 4; ni++) {
                int n = nq * 32 + ni * 8 + r;
                unsigned b0 = *(unsigned*)&Bs[cur][n][c2];
                unsigned b1 = *(unsigned*)&Bs[cur][n][c2 + 8];
                mma16(acc[mi][ni], a0, a1, a2, a3, b0, b1);
            }
        }
        if (ks < 63) {
            *(uint4*)&As[cur ^ 1][lrow][lseg] = na;
            *(uint4*)&Bs[cur ^ 1][lrow][lseg] = nb;
        }
    }
#pragma unroll
    for (int mi = 0; mi < 4; mi++) {
        int row = r0 + mh * 64 + mi * 16 + r;
#pragma unroll
        for (int ni = 0; ni < 4; ni++) {
            int col = v0 + nq * 32 + ni * 8 + c2;
            float b0 = bp[col], b1 = bp[col + 1];
            dLog[(size_t)row * V_ + col] = acc[mi][ni][0] + b0;
            dLog[(size_t)row * V_ + col + 1] = acc[mi][ni][1] + b1;
            dLog[(size_t)(row + 8) * V_ + col] = acc[mi][ni][2] + b0;
            dLog[(size_t)(row + 8) * V_ + col + 1] = acc[mi][ni][3] + b1;
        }
    }
}

// ---------------- softmax + mixture log output ----------------
__global__ void softmax_out(float* __restrict__ out) {
    int rr = blockIdx.x, tid = threadIdx.x;
    const float* L = dLog + (size_t)rr * V_;
    __shared__ float rm[256], rs[256];
    float m = -1e30f, s = 0.f;
    for (int v = tid; v < V_; v += 256) {
        float x = L[v];
        if (x > m) { s = fmaf(s, fexp(m - x), 1.0f); m = x; }
        else s += fexp(x - m);
    }
    rm[tid] = m; rs[tid] = s; __syncthreads();
    for (int st = 128; st; st >>= 1) {
        if (tid < st) {
            float m2 = rm[tid + st], s2 = rs[tid + st];
            float M = fmaxf(rm[tid], m2);
            rs[tid] = rs[tid] * fexp(rm[tid] - M) + s2 * fexp(m2 - M);
            rm[tid] = M;
        }
        __syncthreads();
    }
    m = rm[0];
    float inv = 1.0f / rs[0];
    float cw = fexp(L[3] - m) * inv;          // COPY_ID = 3
    if (tid == 0) { dMx[rr] = m; dIs[rr] = inv; dCw[rr] = cw; }
    float ce = cw * 1e-7f, oc = (1.0f - cw) * inv;
    float* O = out + (size_t)rr * V_;
    for (int v = tid; v < V_; v += 256)
        O[v] = flog(fmaf(oc, fexp(L[v] - m), ce));
}

__global__ void fixup(float* __restrict__ out, const int* __restrict__ tok) {
    int rr = blockIdx.x;
    int t = rr >> 5, b = rr & 31;
    int s = threadIdx.x;
    __shared__ int tk[T_];
    __shared__ float dd[T_];
    tk[s] = tok[s * 32 + b];
    dd[s] = dDist[(t * T_ + s) * 32 + b];
    __syncthreads();
    int mytok = tk[s];
    float tot = 0.f;
    for (int s2 = 0; s2 < T_; s2++) if (tk[s2] == mytok) tot += dd[s2];
    float m = dMx[rr], inv = dIs[rr], cw = dCw[rr];
    float p = fexp(dLog[(size_t)rr * V_ + mytok] - m) * inv;
    out[(size_t)rr * V_ + mytok] = flog(cw * (1e-7f + tot) + (1.0f - cw) * p);
}

// ---------------- host ----------------
extern "C" void kernel_launch(void* const* d_in, const int* in_sizes, int n_in,
                              void* d_out, int out_size) {
    const int* tok = (const int*)d_in[0];
    const float* h0 = (const float*)d_in[1];
    const float* c0 = (const float*)d_in[2];
    const float* Eb = (const float*)d_in[3];
    const float* Wih0 = (const float*)d_in[4];
    const float* Whh0 = (const float*)d_in[5];
    const float* bih0 = (const float*)d_in[6];
    const float* bhh0 = (const float*)d_in[7];
    const float* Wih1 = (const float*)d_in[8];
    const float* Whh1 = (const float*)d_in[9];
    const float* bih1 = (const float*)d_in[10];
    const float* bhh1 = (const float*)d_in[11];
    const float* Wk = (const float*)d_in[12];
    const float* bk = (const float*)d_in[13];
    const float* Wc = (const float*)d_in[14];
    const float* bc = (const float*)d_in[15];
    const float* Wp = (const float*)d_in[16];
    const float* bp = (const float*)d_in[17];
    float* out = (float*)d_out;

    pk_big<<<4096, 256>>>(Wih0, Whh0, Wih1, Whh1);           // launch 0
    pk_small<<<4096, 256>>>(Wk, Wc, Wp);                     // launch 1
    pk_state<<<128, 256>>>(bih0, bhh0, bih1, bhh1, h0, c0, Eb, tok);  // launch 2
    decode_loop<<<NBLK, 256>>>(tok, Eb, bk, bc);             // launch 3 (profiled)
    gemm_logits<<<dim3(V_ / 128, (T_ * B_) / 128), 256>>>(bp);
    softmax_out<<<T_ * B_, 256>>>(out);
    fixup<<<T_ * B_, 64>>>(out, tok);
}

// round 11
// speedup vs baseline: 6.9278x; 1.0230x over previous
#include <cuda_runtime.h>
#include <cuda_bf16.h>
#include <stdint.h>
#include <math.h>

#define T_ 64
#define B_ 32
#define V_ 32000
#define H_ 1024
#define K0_ 2560
#define K1_ 2048
#define NBLK 128

// ---------------- device scratch ----------------
__device__ uint4 dW0p[(size_t)4096 * K0_ / 8];
__device__ uint4 dW1p[(size_t)4096 * K1_ / 8];
__device__ uint4 dWkp[(size_t)H_ * H_ / 8];
__device__ uint4 dWc1p[(size_t)H_ * H_ / 8];
__device__ uint4 dWc2p[(size_t)H_ * H_ / 8];
__device__ __nv_bfloat16 dWp[(size_t)V_ * H_];
__device__ float dB0[4096], dB1[4096];
__device__ uint4 dX0p[2][(K0_ / 16) * 64];
__device__ uint4 dX1p[2][(K1_ / 16) * 64];
__device__ uint4 dXcp[(H_ / 16) * 64];
__device__ float dC0[B_ * H_], dC1[B_ * H_];
__device__ float dQ[H_ * B_];
__device__ float dCb1[H_ * B_];
__device__ float dM[(size_t)T_ * B_ * H_];
__device__ __nv_bfloat16 dHBh[(size_t)T_ * B_ * H_];
__device__ float dDist[T_ * T_ * B_];
__device__ __nv_bfloat16 dA[(size_t)T_ * B_ * H_];
__device__ float dMx[T_ * B_], dIs[T_ * B_], dCw[T_ * B_];
__device__ float dLog[(size_t)T_ * B_ * V_];
__device__ int gCnt;
__device__ int gRel;

// ---------------- fast transcendentals (FMA pipe) ----------------
__device__ __forceinline__ float fexp(float x) {
    float t = fminf(fmaxf(x * 1.44269504f, -126.0f), 126.0f);
    float r = rintf(t);
    float f = t - r;
    float p = 1.3333558146e-3f;
    p = fmaf(p, f, 9.6181291076e-3f);
    p = fmaf(p, f, 5.5504108664e-2f);
    p = fmaf(p, f, 2.4022650696e-1f);
    p = fmaf(p, f, 6.9314718056e-1f);
    p = fmaf(p, f, 1.0f);
    return p * __int_as_float(((int)r + 127) << 23);
}
__device__ __forceinline__ float flog(float x) {
    int ix = __float_as_int(x);
    int e = (ix >> 23) - 127;
    float m = __int_as_float((ix & 0x7FFFFF) | 0x3F800000);
    if (m > 1.41421356f) { m *= 0.5f; e++; }
    float f = m - 1.0f;
    float z = f * f;
    float p = 7.0376836292e-2f;
    p = fmaf(p, f, -1.1514610310e-1f);
    p = fmaf(p, f, 1.1676998740e-1f);
    p = fmaf(p, f, -1.2420140846e-1f);
    p = fmaf(p, f, 1.4249322787e-1f);
    p = fmaf(p, f, -1.6668057665e-1f);
    p = fmaf(p, f, 2.0000714765e-1f);
    p = fmaf(p, f, -2.4999993993e-1f);
    p = fmaf(p, f, 3.3333331174e-1f);
    float y = fmaf(p * f, z, -0.5f * z) + f;
    return fmaf((float)e, 0.69314718056f, y);
}
__device__ __forceinline__ float fsig(float x) {
    return __fdividef(1.0f, 1.0f + fexp(-x));
}
__device__ __forceinline__ float ftanh(float x) {
    float e = fexp(-2.0f * fabsf(x));
    float t = __fdividef(1.0f - e, 1.0f + e);
    return x >= 0.f ? t : -t;
}

__device__ __forceinline__ int xpk(int n, int k) {
    int p = k >> 4, hi = (k >> 3) & 1, lo = k & 1, ci = (k >> 1) & 3;
    int nh = n >> 4, rh = (n >> 3) & 1, r = n & 7;
    return ((((p * 2 + nh) * 32 + (r * 4 + ci)) * 4) + (rh * 2 + hi)) * 2 + lo;
}

__device__ __forceinline__ float ldcgf(const float* p) {
    float v; asm volatile("ld.global.cg.f32 %0,[%1];" : "=f"(v) : "l"(p)); return v;
}
__device__ __forceinline__ uint4 ldcg4(const void* p) {
    uint4 v;
    asm volatile("ld.global.cg.v4.b32 {%0,%1,%2,%3},[%4];"
                 : "=r"(v.x), "=r"(v.y), "=r"(v.z), "=r"(v.w) : "l"(p));
    return v;
}
__device__ __forceinline__ uint4 ldg4(const void* p) {    // cached (L1) but order-pinned
    uint4 v;
    asm volatile("ld.global.v4.b32 {%0,%1,%2,%3},[%4];"
                 : "=r"(v.x), "=r"(v.y), "=r"(v.z), "=r"(v.w) : "l"(p));
    return v;
}
__device__ __forceinline__ void st_rel(int* p, int v) {
    asm volatile("st.release.gpu.global.s32 [%0],%1;" :: "l"(p), "r"(v) : "memory");
}
__device__ __forceinline__ int ld_acq(const int* p) {
    int v; asm volatile("ld.acquire.gpu.global.s32 %0,[%1];" : "=r"(v) : "l"(p) : "memory");
    return v;
}
__device__ __forceinline__ int atom_add_rel(int* p, int v) {
    int old;
    asm volatile("atom.release.gpu.global.add.s32 %0,[%1],%2;"
                 : "=r"(old) : "l"(p), "r"(v) : "memory");
    return old;
}
__device__ __forceinline__ void mma16(float c[4], unsigned a0, unsigned a1,
                                      unsigned a2, unsigned a3, unsigned b0, unsigned b1) {
    asm volatile("mma.sync.aligned.m16n8k16.row.col.f32.bf16.bf16.f32 "
                 "{%0,%1,%2,%3},{%4,%5,%6,%7},{%8,%9},{%0,%1,%2,%3};"
                 : "+f"(c[0]), "+f"(c[1]), "+f"(c[2]), "+f"(c[3])
                 : "r"(a0), "r"(a1), "r"(a2), "r"(a3), "r"(b0), "r"(b1));
}

// ---------------- grid barrier ----------------
__device__ __forceinline__ void gbar(int e) {
    __syncthreads();
    if (threadIdx.x == 0) {
        int v = atom_add_rel(&gCnt, 1);
        if (v == e * NBLK - 1) st_rel(&gRel, e);
        else while (ld_acq(&gRel) < e) { }
    }
    __syncthreads();
}

// ---------------- pipelined 32x32xKC GEMM: 16 warps = 8 kseg x 2 nhalf ----------------
// Each warp: 32x16 output over its K/8 segment, double-buffered groups of 2 panels.
template <int KC>
__device__ __forceinline__ void gemm_p(const uint4* __restrict__ Wt,
                                       const uint4* __restrict__ Xp,
                                       float (*G)[32][33]) {
    int tid = threadIdx.x, wid = tid >> 5, lane = tid & 31;
    int ks = wid & 7, nh = wid >> 3;
    constexpr int PPW = KC / 128;          // panels per k-segment (20/16/8)
    constexpr int NG = PPW / 2;            // groups of 2 panels
    const uint4* Wr = Wt + (size_t)(ks * PPW * 2) * 32 + lane;
    const uint4* Xr = Xp + (size_t)(ks * PPW * 2) * 32 + nh * 32 + lane;
    float c[2][2][4];
#pragma unroll
    for (int i = 0; i < 2; i++)
#pragma unroll
        for (int j = 0; j < 2; j++)
#pragma unroll
            for (int k = 0; k < 4; k++) c[i][j][k] = 0.f;
    uint4 a0[2][2], a1[2][2], xb[2][2];
#pragma unroll
    for (int q = 0; q < 2; q++) {          // prologue: group 0 -> buf 0
        a0[0][q] = ldg4(Wr + q * 64);
        a1[0][q] = ldg4(Wr + q * 64 + 32);
        xb[0][q] = ldcg4(Xr + q * 64);
    }
#pragma unroll
    for (int pg = 0; pg < NG; pg++) {
        int cb = pg & 1, nb = cb ^ 1;
        if (pg + 1 < NG) {                 // prefetch next group (6 loads, order-pinned)
#pragma unroll
            for (int q = 0; q < 2; q++) {
                int p = (pg + 1) * 2 + q;
                a0[nb][q] = ldg4(Wr + p * 64);
                a1[nb][q] = ldg4(Wr + p * 64 + 32);
                xb[nb][q] = ldcg4(Xr + p * 64);
            }
        }
#pragma unroll
        for (int q = 0; q < 2; q++) {
            mma16(c[0][0], a0[cb][q].x, a0[cb][q].y, a0[cb][q].z, a0[cb][q].w,
                  xb[cb][q].x, xb[cb][q].y);
            mma16(c[0][1], a0[cb][q].x, a0[cb][q].y, a0[cb][q].z, a0[cb][q].w,
                  xb[cb][q].z, xb[cb][q].w);
            mma16(c[1][0], a1[cb][q].x, a1[cb][q].y, a1[cb][q].z, a1[cb][q].w,
                  xb[cb][q].x, xb[cb][q].y);
            mma16(c[1][1], a1[cb][q].x, a1[cb][q].y, a1[cb][q].z, a1[cb][q].w,
                  xb[cb][q].z, xb[cb][q].w);
        }
    }
    int r = lane >> 2, c2 = (lane & 3) * 2;
#pragma unroll
    for (int mh = 0; mh < 2; mh++)
#pragma unroll
        for (int q = 0; q < 2; q++) {
            int row = mh * 16 + r, col = nh * 16 + q * 8 + c2;
            G[ks][row][col] = c[mh][q][0];
            G[ks][row][col + 1] = c[mh][q][1];
            G[ks][row + 8][col] = c[mh][q][2];
            G[ks][row + 8][col + 1] = c[mh][q][3];
        }
}
__device__ __forceinline__ float gsum(float (*G)[32][33], int row, int b) {
    float s = 0.f;
#pragma unroll
    for (int k = 0; k < 8; k++) s += G[k][row][b];
    return s;
}

// ---------------- persistent decode loop: 512 threads, 4 phases/step ----------------
__global__ void __launch_bounds__(512, 1)
decode_loop(const int* __restrict__ tok, const float* __restrict__ Eb,
            const float* __restrict__ bk, const float* __restrict__ bc) {
    __shared__ __align__(16) float Gs[8][32][33];
    int bid = blockIdx.x, tid = threadIdx.x;
    int b = tid & 31;
    int e = 0;
    const uint4* W0t = dW0p + (size_t)bid * (160 * 64);
    const uint4* W1t = dW1p + (size_t)bid * (128 * 64);

    for (int t = 0; t < T_; t++) {
        int cur = t & 1, nxt = cur ^ 1;

        // ---- Phase A: layer-0 GEMM + LSTM pointwise ----
        gemm_p<K0_>(W0t, dX0p[cur], Gs);
        __syncthreads();
        if (tid < 256) {
            int hl = tid >> 5;
            int h = bid * 8 + hl, j0 = bid * 32 + hl * 4;
            float g0 = gsum(Gs, hl * 4 + 0, b) + dB0[j0 + 0];
            float g1 = gsum(Gs, hl * 4 + 1, b) + dB0[j0 + 1];
            float g2 = gsum(Gs, hl * 4 + 2, b) + dB0[j0 + 2];
            float g3 = gsum(Gs, hl * 4 + 3, b) + dB0[j0 + 3];
            float c = dC0[h * 32 + b];
            float cn = fsig(g1) * c + fsig(g0) * ftanh(g2);
            float hn = fsig(g3) * ftanh(cn);
            dC0[h * 32 + b] = cn;
            __nv_bfloat16 hb = __float2bfloat16(hn);
            ((__nv_bfloat16*)dX1p[cur])[xpk(b, h)] = hb;
            ((__nv_bfloat16*)dX0p[nxt])[xpk(b, 1536 + h)] = hb;
        }
        gbar(++e);

        // ---- Phase B: layer-1 GEMM + LSTM pointwise ----
        gemm_p<K1_>(W1t, dX1p[cur], Gs);
        __syncthreads();
        if (tid < 256) {
            int hl = tid >> 5;
            int h = bid * 8 + hl, j0 = bid * 32 + hl * 4;
            float g0 = gsum(Gs, hl * 4 + 0, b) + dB1[j0 + 0];
            float g1 = gsum(Gs, hl * 4 + 1, b) + dB1[j0 + 1];
            float g2 = gsum(Gs, hl * 4 + 2, b) + dB1[j0 + 2];
            float g3 = gsum(Gs, hl * 4 + 3, b) + dB1[j0 + 3];
            float c = dC1[h * 32 + b];
            float cn = fsig(g1) * c + fsig(g0) * ftanh(g2);
            float hn = fsig(g3) * ftanh(cn);
            dC1[h * 32 + b] = cn;
            __nv_bfloat16 hb = __float2bfloat16(hn);
            ((__nv_bfloat16*)dXcp)[xpk(b, h)] = hb;
            ((__nv_bfloat16*)dX1p[nxt])[xpk(b, 1024 + h)] = hb;
            dHBh[((size_t)t * 32 + b) * H_ + h] = hb;
        }
        gbar(++e);

        // ---- Phase C: q/M/comb1 GEMMs + emb prefetch ----
        if (bid < 32) {
            gemm_p<H_>(dWkp + (size_t)bid * 4096, dXcp, Gs);
            __syncthreads();
            int rl = tid >> 5;
            dQ[(bid * 32 + rl) * 32 + b] = gsum(Gs, rl, b);
            dQ[(bid * 32 + rl + 16) * 32 + b] = gsum(Gs, rl + 16, b);
        } else if (bid < 64) {
            int jt = bid - 32;
            gemm_p<H_>(dWc2p + (size_t)jt * 4096, dXcp, Gs);
            __syncthreads();
            int rl = tid >> 5;
            dM[((size_t)t * 32 + b) * H_ + jt * 32 + rl] = gsum(Gs, rl, b);
            dM[((size_t)t * 32 + b) * H_ + jt * 32 + rl + 16] = gsum(Gs, rl + 16, b);
        } else if (bid < 96) {
            int jt = bid - 64;
            gemm_p<H_>(dWc1p + (size_t)jt * 4096, dXcp, Gs);
            __syncthreads();
            int rl = tid >> 5;
            dCb1[(jt * 32 + rl) * 32 + b] = gsum(Gs, rl, b);
            dCb1[(jt * 32 + rl + 16) * 32 + b] = gsum(Gs, rl + 16, b);
        } else if (t + 1 < T_) {
            int bb = bid - 96;
            int tk = tok[(t + 1) * 32 + bb];
            if (tid < 512)
                ((__nv_bfloat16*)dX0p[nxt])[xpk(bb, tid)] =
                    __float2bfloat16(Eb[(size_t)tk * 512 + tid]);
        }
        gbar(++e);

        // ---- Phase D: attention + comb finalize (32 blocks, 512 threads) ----
        if (bid < 32) {
            int bb = bid;
            float* qv = (float*)Gs;          // 1024
            float* sc = qv + 1024;           // 64
            float* red = sc + 64;            // 512
            int h2 = tid * 2;
            {
                qv[h2] = ldcgf(&dQ[h2 * 32 + bb]);
                qv[h2 + 1] = ldcgf(&dQ[(h2 + 1) * 32 + bb]);
                const __nv_bfloat16* ht = &dHBh[((size_t)t * 32 + bb) * H_ + h2];
                red[tid] = __bfloat162float(ht[0]) * bk[h2]
                         + __bfloat162float(ht[1]) * bk[h2 + 1];
            }
            __syncthreads();
            for (int st = 256; st; st >>= 1) { if (tid < st) red[tid] += red[tid + st]; __syncthreads(); }
            float bkh = red[0];
            __syncthreads();
            int w = tid >> 5, lane = tid & 31;
            for (int si = w; si <= t; si += 16) {
                const __nv_bfloat16* hr = &dHBh[((size_t)si * 32 + bb) * H_];
                float acc = 0.f;
                for (int h = lane * 8; h < H_; h += 256) {
                    uint4 hv = *(const uint4*)(hr + h);
                    float2 a0 = __bfloat1622float2(*(__nv_bfloat162*)&hv.x);
                    float2 a1 = __bfloat1622float2(*(__nv_bfloat162*)&hv.y);
                    float2 a2 = __bfloat1622float2(*(__nv_bfloat162*)&hv.z);
                    float2 a3 = __bfloat1622float2(*(__nv_bfloat162*)&hv.w);
                    acc += a0.x * qv[h] + a0.y * qv[h + 1] + a1.x * qv[h + 2] + a1.y * qv[h + 3]
                         + a2.x * qv[h + 4] + a2.y * qv[h + 5] + a3.x * qv[h + 6] + a3.y * qv[h + 7];
                }
#pragma unroll
                for (int o = 16; o; o >>= 1) acc += __shfl_xor_sync(0xffffffffu, acc, o);
                if (!lane) {
                    float v = acc + bkh;
                    if (tok[si * 32 + bb] == 0) v += -99999.0f;
                    sc[si] = v;
                }
            }
            __syncthreads();
            float v = (tid < 64 && tid <= t) ? sc[tid] : -1e30f;
            red[tid] = v; __syncthreads();
            for (int st = 256; st; st >>= 1) { if (tid < st) red[tid] = fmaxf(red[tid], red[tid + st]); __syncthreads(); }
            float m = red[0]; __syncthreads();
            float ev = (tid < 64 && tid <= t) ? fexp(v - m) : 0.f;
            red[tid] = ev; __syncthreads();
            for (int st = 256; st; st >>= 1) { if (tid < st) red[tid] += red[tid + st]; __syncthreads(); }
            float inv = 1.0f / red[0];
            if (tid < 64) sc[tid] = (tid <= t) ? ev * inv : 0.f;
            __syncthreads();
            if (tid < 64) dDist[(t * T_ + tid) * 32 + bb] = sc[tid];
            {
                int j = tid * 2;
                float a0 = ldcgf(&dCb1[(j + 0) * 32 + bb]);
                float a1 = ldcgf(&dCb1[(j + 1) * 32 + bb]);
#pragma unroll 4
                for (int s = 0; s <= t; s++) {
                    float d = sc[s];
                    float2 mv = *(const float2*)&dM[((size_t)s * 32 + bb) * H_ + j];
                    a0 = fmaf(d, mv.x, a0); a1 = fmaf(d, mv.y, a1);
                }
                a0 += bc[j]; a1 += bc[j + 1];
                __nv_bfloat162 p0 = __floats2bfloat162_rn(a0, a1);
                ((unsigned*)dX0p[nxt])[xpk(bb, 512 + j) >> 1] = *(unsigned*)&p0;
                *(unsigned*)&dA[((size_t)t * 32 + bb) * H_ + j] = *(unsigned*)&p0;
            }
        }
        gbar(++e);
    }
}

// ---------------- prep kernel 0: pack W0 + W1 ----------------
__global__ void pk_big(const float* __restrict__ Wih0, const float* __restrict__ Whh0,
                       const float* __restrict__ Wih1, const float* __restrict__ Whh1) {
    const size_t N0 = (size_t)4096 * K0_ / 8;
    const size_t N1 = (size_t)4096 * K1_ / 8;
    for (size_t uu = (size_t)blockIdx.x * blockDim.x + threadIdx.x; uu < N0 + N1;
         uu += (size_t)gridDim.x * blockDim.x) {
        bool first = uu < N0;
        size_t u = first ? uu : uu - N0;
        int PAN = first ? 160 : 128;
        const float* Wih = first ? Wih0 : Wih1;
        const float* Whh = first ? Whh0 : Whh1;
        int KIH = first ? 1536 : 1024;
        int lane = (int)(u & 31); size_t t1 = u >> 5; int mh = (int)(t1 & 1); size_t t2 = t1 >> 1;
        int p = (int)(t2 % PAN); int jt = (int)(t2 / PAN);
        int r = lane >> 2, ci = lane & 3;
        unsigned o[4];
#pragma unroll
        for (int reg = 0; reg < 4; reg++) {
            int rh = reg & 1, hi = reg >> 1;
            int row = jt * 32 + mh * 16 + rh * 8 + r;
            int orow = (row & 3) * 1024 + (row >> 2);
            int col = p * 16 + hi * 8 + ci * 2;
            float v0, v1;
            if (col < KIH) { v0 = Wih[(size_t)orow * KIH + col]; v1 = Wih[(size_t)orow * KIH + col + 1]; }
            else { v0 = Whh[(size_t)orow * 1024 + col - KIH]; v1 = Whh[(size_t)orow * 1024 + col - KIH + 1]; }
            __nv_bfloat162 bb = __floats2bfloat162_rn(v0, v1);
            o[reg] = *(unsigned*)&bb;
        }
        if (first) dW0p[u] = make_uint4(o[0], o[1], o[2], o[3]);
        else dW1p[u] = make_uint4(o[0], o[1], o[2], o[3]);
    }
}

// ---------------- prep kernel 1: pack Wk^T/Wc1/Wc2 + cast Wp ----------------
__global__ void pk_small(const float* __restrict__ Wk, const float* __restrict__ Wc,
                         const float* __restrict__ Wp) {
    const size_t NP = (size_t)H_ * H_ / 8;
    const size_t NW = (size_t)V_ * H_ / 8;
    for (size_t uu = (size_t)blockIdx.x * blockDim.x + threadIdx.x; uu < 3 * NP + NW;
         uu += (size_t)gridDim.x * blockDim.x) {
        if (uu < 3 * NP) {
            int which = (int)(uu / NP);
            size_t rem = uu % NP;
            int lane = (int)(rem & 31); size_t t1 = rem >> 5; int mh = (int)(t1 & 1); size_t t2 = t1 >> 1;
            int p = (int)(t2 % 64); int jt = (int)(t2 / 64);
            int r = lane >> 2, ci = lane & 3;
            unsigned o[4];
#pragma unroll
            for (int reg = 0; reg < 4; reg++) {
                int rh = reg & 1, hi = reg >> 1;
                int row = jt * 32 + mh * 16 + rh * 8 + r;
                int col = p * 16 + hi * 8 + ci * 2;
                float v0, v1;
                if (which == 0) { v0 = Wk[(size_t)col * 1024 + row]; v1 = Wk[(size_t)(col + 1) * 1024 + row]; }
                else if (which == 1) { v0 = Wc[(size_t)row * 2048 + col]; v1 = Wc[(size_t)row * 2048 + col + 1]; }
                else { v0 = Wc[(size_t)row * 2048 + 1024 + col]; v1 = Wc[(size_t)row * 2048 + 1025 + col]; }
                __nv_bfloat162 bb = __floats2bfloat162_rn(v0, v1);
                o[reg] = *(unsigned*)&bb;
            }
            if (which == 0) dWkp[rem] = make_uint4(o[0], o[1], o[2], o[3]);
            else if (which == 1) dWc1p[rem] = make_uint4(o[0], o[1], o[2], o[3]);
            else dWc2p[rem] = make_uint4(o[0], o[1], o[2], o[3]);
        } else {
            size_t w = uu - 3 * NP;
            float4 f0 = *(const float4*)(Wp + w * 8);
            float4 f1 = *(const float4*)(Wp + w * 8 + 4);
            __nv_bfloat162 b0 = __floats2bfloat162_rn(f0.x, f0.y);
            __nv_bfloat162 b1 = __floats2bfloat162_rn(f0.z, f0.w);
            __nv_bfloat162 b2 = __floats2bfloat162_rn(f1.x, f1.y);
            __nv_bfloat162 b3 = __floats2bfloat162_rn(f1.z, f1.w);
            ((uint4*)dWp)[w] = make_uint4(*(unsigned*)&b0, *(unsigned*)&b1,
                                          *(unsigned*)&b2, *(unsigned*)&b3);
        }
    }
}

// ---------------- prep kernel 2: state init ----------------
__global__ void pk_state(const float* __restrict__ bih0, const float* __restrict__ bhh0,
                         const float* __restrict__ bih1, const float* __restrict__ bhh1,
                         const float* __restrict__ h0, const float* __restrict__ c0,
                         const float* __restrict__ Eb, const int* __restrict__ tok) {
    int i = blockIdx.x * blockDim.x + threadIdx.x;   // 32768 threads
    int bb = i >> 10, h = i & 1023;
    dC0[h * 32 + bb] = c0[(size_t)bb * H_ + h];
    dC1[h * 32 + bb] = c0[(size_t)B_ * H_ + (size_t)bb * H_ + h];
    ((__nv_bfloat16*)dX0p[0])[xpk(bb, 1536 + h)] = __float2bfloat16(h0[(size_t)bb * H_ + h]);
    ((__nv_bfloat16*)dX1p[0])[xpk(bb, 1024 + h)] =
        __float2bfloat16(h0[(size_t)B_ * H_ + (size_t)bb * H_ + h]);
    ((__nv_bfloat16*)dX0p[0])[xpk(bb, 512 + h)] = __float2bfloat16(0.0f);
    if (i < 4096) {
        int h2 = i >> 2, g = i & 3;
        dB0[i] = bih0[g * 1024 + h2] + bhh0[g * 1024 + h2];
        dB1[i] = bih1[g * 1024 + h2] + bhh1[g * 1024 + h2];
    }
    if (i < 32 * 512) {
        int b2 = i >> 9, e2 = i & 511;
        ((__nv_bfloat16*)dX0p[0])[xpk(b2, e2)] = __float2bfloat16(Eb[(size_t)tok[b2] * 512 + e2]);
    }
    if (i == 0) { gCnt = 0; gRel = 0; }
}

// ---------------- logits GEMM: 128x128 double-buffered ----------------
__global__ void __launch_bounds__(256) gemm_logits(const float* __restrict__ bp) {
    int v0 = blockIdx.x * 128, r0 = blockIdx.y * 128;
    __shared__ __nv_bfloat16 As[2][128][24];
    __shared__ __nv_bfloat16 Bs[2][128][24];
    int tid = threadIdx.x, wid = tid >> 5, lane = tid & 31;
    int mh = wid >> 2, nq = wid & 3;
    int r = lane >> 2, c2 = (lane & 3) * 2;
    int lrow = tid >> 1, lseg = (tid & 1) * 8;
    float acc[4][4][4];
#pragma unroll
    for (int a = 0; a < 4; a++)
#pragma unroll
        for (int bb = 0; bb < 4; bb++)
#pragma unroll
            for (int c = 0; c < 4; c++) acc[a][bb][c] = 0.f;

    *(uint4*)&As[0][lrow][lseg] = *(const uint4*)&dA[(size_t)(r0 + lrow) * H_ + lseg];
    *(uint4*)&Bs[0][lrow][lseg] = *(const uint4*)&dWp[(size_t)(v0 + lrow) * H_ + lseg];
    for (int ks = 0; ks < 64; ks++) {
        __syncthreads();
        uint4 na, nb;
        if (ks < 63) {
            na = *(const uint4*)&dA[(size_t)(r0 + lrow) * H_ + (ks + 1) * 16 + lseg];
            nb = *(const uint4*)&dWp[(size_t)(v0 + lrow) * H_ + (ks + 1) * 16 + lseg];
        }
        int cur = ks & 1;
#pragma unroll
        for (int mi = 0; mi < 4; mi++) {
            int row = mh * 64 + mi * 16;
            unsigned a0 = *(unsigned*)&As[cur][row + r][c2];
            unsigned a1 = *(unsigned*)&As[cur][row + r + 8][c2];
            unsigned a2 = *(unsigned*)&As[cur][row + r][c2 + 8];
            unsigned a3 = *(unsigned*)&As[cur][row + r + 8][c2 + 8];
#pragma unroll
            for (int ni = 0; ni < 4; ni++) {
                int n = nq * 32 + ni * 8 + r;
                unsigned b0 = *(unsigned*)&Bs[cur][n][c2];
                unsigned b1 = *(unsigned*)&Bs[cur][n][c2 + 8];
                mma16(acc[mi][ni], a0, a1, a2, a3, b0, b1);
            }
        }
        if (ks < 63) {
            *(uint4*)&As[cur ^ 1][lrow][lseg] = na;
            *(uint4*)&Bs[cur ^ 1][lrow][lseg] = nb;
        }
    }
#pragma unroll
    for (int mi = 0; mi < 4; mi++) {
        int row = r0 + mh * 64 + mi * 16 + r;
#pragma unroll
        for (int ni = 0; ni < 4; ni++) {
            int col = v0 + nq * 32 + ni * 8 + c2;
            float b0 = bp[col], b1 = bp[col + 1];
            dLog[(size_t)row * V_ + col] = acc[mi][ni][0] + b0;
            dLog[(size_t)row * V_ + col + 1] = acc[mi][ni][1] + b1;
            dLog[(size_t)(row + 8) * V_ + col] = acc[mi][ni][2] + b0;
            dLog[(size_t)(row + 8) * V_ + col + 1] = acc[mi][ni][3] + b1;
        }
    }
}

// ---------------- softmax + mixture log output ----------------
__global__ void softmax_out(float* __restrict__ out) {
    int rr = blockIdx.x, tid = threadIdx.x;
    const float* L = dLog + (size_t)rr * V_;
    __shared__ float rm[256], rs[256];
    float m = -1e30f, s = 0.f;
    for (int v = tid; v < V_; v += 256) {
        float x = L[v];
        if (x > m) { s = fmaf(s, fexp(m - x), 1.0f); m = x; }
        else s += fexp(x - m);
    }
    rm[tid] = m; rs[tid] = s; __syncthreads();
    for (int st = 128; st; st >>= 1) {
        if (tid < st) {
            float m2 = rm[tid + st], s2 = rs[tid + st];
            float M = fmaxf(rm[tid], m2);
            rs[tid] = rs[tid] * fexp(rm[tid] - M) + s2 * fexp(m2 - M);
            rm[tid] = M;
        }
        __syncthreads();
    }
    m = rm[0];
    float inv = 1.0f / rs[0];
    float cw = fexp(L[3] - m) * inv;          // COPY_ID = 3
    if (tid == 0) { dMx[rr] = m; dIs[rr] = inv; dCw[rr] = cw; }
    float ce = cw * 1e-7f, oc = (1.0f - cw) * inv;
    float* O = out + (size_t)rr * V_;
    for (int v = tid; v < V_; v += 256)
        O[v] = flog(fmaf(oc, fexp(L[v] - m), ce));
}

__global__ void fixup(float* __restrict__ out, const int* __restrict__ tok) {
    int rr = blockIdx.x;
    int t = rr >> 5, b = rr & 31;
    int s = threadIdx.x;
    __shared__ int tk[T_];
    __shared__ float dd[T_];
    tk[s] = tok[s * 32 + b];
    dd[s] = dDist[(t * T_ + s) * 32 + b];
    __syncthreads();
    int mytok = tk[s];
    float tot = 0.f;
    for (int s2 = 0; s2 < T_; s2++) if (tk[s2] == mytok) tot += dd[s2];
    float m = dMx[rr], inv = dIs[rr], cw = dCw[rr];
    float p = fexp(dLog[(size_t)rr * V_ + mytok] - m) * inv;
    out[(size_t)rr * V_ + mytok] = flog(cw * (1e-7f + tot) + (1.0f - cw) * p);
}

// ---------------- host ----------------
extern "C" void kernel_launch(void* const* d_in, const int* in_sizes, int n_in,
                              void* d_out, int out_size) {
    const int* tok = (const int*)d_in[0];
    const float* h0 = (const float*)d_in[1];
    const float* c0 = (const float*)d_in[2];
    const float* Eb = (const float*)d_in[3];
    const float* Wih0 = (const float*)d_in[4];
    const float* Whh0 = (const float*)d_in[5];
    const float* bih0 = (const float*)d_in[6];
    const float* bhh0 = (const float*)d_in[7];
    const float* Wih1 = (const float*)d_in[8];
    const float* Whh1 = (const float*)d_in[9];
    const float* bih1 = (const float*)d_in[10];
    const float* bhh1 = (const float*)d_in[11];
    const float* Wk = (const float*)d_in[12];
    const float* bk = (const float*)d_in[13];
    const float* Wc = (const float*)d_in[14];
    const float* bc = (const float*)d_in[15];
    const float* Wp = (const float*)d_in[16];
    const float* bp = (const float*)d_in[17];
    float* out = (float*)d_out;

    pk_big<<<4096, 256>>>(Wih0, Whh0, Wih1, Whh1);           // launch 0
    pk_small<<<4096, 256>>>(Wk, Wc, Wp);                     // launch 1
    pk_state<<<128, 256>>>(bih0, bhh0, bih1, bhh1, h0, c0, Eb, tok);  // launch 2
    decode_loop<<<NBLK, 512>>>(tok, Eb, bk, bc);             // launch 3 (profiled)
    gemm_logits<<<dim3(V_ / 128, (T_ * B_) / 128), 256>>>(bp);
    softmax_out<<<T_ * B_, 256>>>(out);
    fixup<<<T_ * B_, 64>>>(out, tok);
}